// round 1
// baseline (speedup 1.0000x reference)
#include <cuda_runtime.h>
#include <cmath>
#include <complex>
#include <algorithm>

// ---------------- problem constants ----------------
#define MTOT 9        // (LMAX+1)^2
#define CCH  128      // channels
#define KNB  16       // neighbors
#define HH   8        // heads
#define MAXN 4096     // max nodes (matches setup)
#define NT   8        // nodes per block in so3lin

struct W3J { float v[210]; };   // packed per-path: (0,1)@0:9 (1,0)@9:9 (1,1)@18:27 (1,2)@45:45 (2,1)@90:45 (2,2)@135:75

// ---------------- scratch (static device globals; no allocation) ----------------
__device__ float g_exp_h1[MAXN * MTOT * CCH];
__device__ float g_c2src [MAXN * MTOT * CCH];
__device__ float g_cdiff [MAXN * MTOT * CCH];

// ======================================================================
// Host-side real Wigner-3j construction (port of the e3nn-style reference)
// ======================================================================
static double hfact(int n){ double r=1.0; for(int i=2;i<=n;i++) r*= (double)i; return r; }

static double su2_cg(int j1,int j2,int j3,int m1,int m2,int m3){
  if(m3 != m1+m2) return 0.0;
  if(j3 < std::abs(j1-j2) || j3 > j1+j2) return 0.0;
  double pref = std::sqrt((2.0*j3+1.0)*hfact(j1+j2-j3)*hfact(j1-j2+j3)*hfact(-j1+j2+j3)/hfact(j1+j2+j3+1));
  pref *= std::sqrt(hfact(j3+m3)*hfact(j3-m3)*hfact(j1-m1)*hfact(j1+m1)*hfact(j2-m2)*hfact(j2+m2));
  int vmin = std::max(0, std::max(j2-j3-m1, j1-j3+m2));
  int vmax = std::min(j1+j2-j3, std::min(j1-m1, j2+m2));
  double s=0.0;
  for(int v=vmin; v<=vmax; v++){
    double den = hfact(v)*hfact(j1+j2-j3-v)*hfact(j1-m1-v)*hfact(j2+m2-v)*hfact(j3-j2+m1+v)*hfact(j3-j1-m2+v);
    s += ((v&1)? -1.0 : 1.0)/den;
  }
  return pref*s;
}

static void q_r2c(int l, std::complex<double>* q){
  int n = 2*l+1;
  for(int i=0;i<n*n;i++) q[i]=std::complex<double>(0.0,0.0);
  double is2 = 1.0/std::sqrt(2.0);
  for(int m=-l;m<0;m++){
    q[(l+m)*n + (l-m)] = std::complex<double>(is2, 0.0);   // col l+|m|
    q[(l+m)*n + (l+m)] = std::complex<double>(0.0,-is2);   // col l-|m|
  }
  q[l*n + l] = std::complex<double>(1.0,0.0);
  for(int m=1;m<=l;m++){
    double sg = (m&1)? -1.0 : 1.0;
    q[(l+m)*n + (l+m)] = std::complex<double>(sg*is2, 0.0);
    q[(l+m)*n + (l-m)] = std::complex<double>(0.0, sg*is2);
  }
  std::complex<double> f(1.0,0.0), mi(0.0,-1.0);
  for(int i=0;i<l;i++) f *= mi;       // (-i)^l
  for(int i=0;i<n*n;i++) q[i] *= f;
}

static void real_w3j(int l1, int l3, float* out){
  const int n1=2*l1+1, n2=3, n3=2*l3+1;
  std::complex<double> Cc[5*3*5];
  for(int i=0;i<n1;i++) for(int j=0;j<n2;j++) for(int k=0;k<n3;k++)
    Cc[(i*n2+j)*n3+k] = std::complex<double>(su2_cg(l1,1,l3, i-l1, j-1, k-l3), 0.0);
  std::complex<double> Q1[25],Q2[9],Q3[25];
  q_r2c(l1,Q1); q_r2c(1,Q2); q_r2c(l3,Q3);
  std::complex<double> C[5*3*5];
  for(int a=0;a<n1;a++) for(int b=0;b<n2;b++) for(int c=0;c<n3;c++){
    std::complex<double> s(0.0,0.0);
    for(int i=0;i<n1;i++) for(int j=0;j<n2;j++) for(int k=0;k<n3;k++)
      s += Q1[i*n1+a]*Q2[j*n2+b]*std::conj(Q3[k*n3+c])*Cc[(i*n2+j)*n3+k];
    C[(a*n2+b)*n3+c]=s;
  }
  double sr=0.0, si=0.0;
  for(int i=0;i<n1*n2*n3;i++){ sr += std::fabs(C[i].real()); si += std::fabs(C[i].imag()); }
  double vals[75]; double norm=0.0;
  for(int i=0;i<n1*n2*n3;i++){ double v=(sr>=si)? C[i].real() : C[i].imag(); vals[i]=v; norm+=v*v; }
  norm = std::sqrt(norm);
  double sc = std::sqrt((double)(2*l3+1))/norm;   // CG 'component' normalization
  for(int i=0;i<n1*n2*n3;i++) out[i] = (float)(vals[i]*sc);
}

static void build_w3j(W3J* w){
  real_w3j(0,1, w->v+0);
  real_w3j(1,0, w->v+9);
  real_w3j(1,1, w->v+18);
  real_w3j(1,2, w->v+45);
  real_w3j(2,1, w->v+90);
  real_w3j(2,2, w->v+135);
}

// ======================================================================
// Device: depthwise uvu tensor product of one (node, channel) point
// x[9] features, y[3] scaled l=1 vector, tpw[6] per-path channel weight.
// ======================================================================
__device__ __forceinline__ void tp_point(const float* x, const float* y, const float* tpw,
                                         const W3J& w, float* o){
  #pragma unroll
  for(int m=0;m<MTOT;m++) o[m]=0.0f;
  float p0[3], p1[9], p2[15];
  #pragma unroll
  for(int b=0;b<3;b++) p0[b] = x[0]*y[b];
  #pragma unroll
  for(int a=0;a<3;a++){
    #pragma unroll
    for(int b=0;b<3;b++) p1[a*3+b] = x[1+a]*y[b];
  }
  #pragma unroll
  for(int a=0;a<5;a++){
    #pragma unroll
    for(int b=0;b<3;b++) p2[a*3+b] = x[4+a]*y[b];
  }
  // path 0: (l1=0 -> l3=1), C[b*3+c]
  #pragma unroll
  for(int c=0;c<3;c++){
    float t=0.f;
    #pragma unroll
    for(int b=0;b<3;b++) t = fmaf(w.v[0 + b*3 + c], p0[b], t);
    o[1+c] = fmaf(tpw[0], t, o[1+c]);
  }
  // path 1: (1 -> 0), C[(a*3+b)]
  {
    float t=0.f;
    #pragma unroll
    for(int a=0;a<3;a++){
      #pragma unroll
      for(int b=0;b<3;b++) t = fmaf(w.v[9 + a*3 + b], p1[a*3+b], t);
    }
    o[0] = fmaf(tpw[1], t, o[0]);
  }
  // path 2: (1 -> 1), C[(a*3+b)*3+c]
  #pragma unroll
  for(int c=0;c<3;c++){
    float t=0.f;
    #pragma unroll
    for(int a=0;a<3;a++){
      #pragma unroll
      for(int b=0;b<3;b++) t = fmaf(w.v[18 + (a*3+b)*3 + c], p1[a*3+b], t);
    }
    o[1+c] = fmaf(tpw[2], t, o[1+c]);
  }
  // path 3: (1 -> 2), C[(a*3+b)*5+c]
  #pragma unroll
  for(int c=0;c<5;c++){
    float t=0.f;
    #pragma unroll
    for(int a=0;a<3;a++){
      #pragma unroll
      for(int b=0;b<3;b++) t = fmaf(w.v[45 + (a*3+b)*5 + c], p1[a*3+b], t);
    }
    o[4+c] = fmaf(tpw[3], t, o[4+c]);
  }
  // path 4: (2 -> 1), C[(a*3+b)*3+c]
  #pragma unroll
  for(int c=0;c<3;c++){
    float t=0.f;
    #pragma unroll
    for(int a=0;a<5;a++){
      #pragma unroll
      for(int b=0;b<3;b++) t = fmaf(w.v[90 + (a*3+b)*3 + c], p2[a*3+b], t);
    }
    o[1+c] = fmaf(tpw[4], t, o[1+c]);
  }
  // path 5: (2 -> 2), C[(a*3+b)*5+c]
  #pragma unroll
  for(int c=0;c<5;c++){
    float t=0.f;
    #pragma unroll
    for(int a=0;a<5;a++){
      #pragma unroll
      for(int b=0;b<3;b++) t = fmaf(w.v[135 + (a*3+b)*5 + c], p2[a*3+b], t);
    }
    o[4+c] = fmaf(tpw[5], t, o[4+c]);
  }
}

// ======================================================================
// Kernel 1/4: per-degree equivariant linear (3 small GEMMs), fp32 with
// packed fma.rn.f32x2 accumulation. W[l] (64KB) staged in smem; NT nodes
// of x staged in smem; 128 threads; each thread owns 4 output columns.
// ======================================================================
__global__ __launch_bounds__(128, 2)
void so3lin_kernel(const float* __restrict__ x, const float* __restrict__ W,
                   const float* __restrict__ bias, float* __restrict__ out,
                   int N, int applyPN)
{
  extern __shared__ float smem[];
  float* sW = smem;                 // 16384 floats (current l)
  float* sx = smem + 16384;         // NT*9*128 floats
  const int tid = threadIdx.x;
  const int nodeBase = blockIdx.x * NT;

  { // stage x tile (float4)
    const float4* gx = reinterpret_cast<const float4*>(x) + (size_t)nodeBase*MTOT*32;
    float4* sx4 = reinterpret_cast<float4*>(sx);
    const int tot = NT*MTOT*32;
    int lim = (N - nodeBase)*MTOT*32; if(lim > tot) lim = tot; if(lim < 0) lim = 0;
    for(int i=tid;i<tot;i+=128) sx4[i] = (i<lim) ? gx[i] : make_float4(0.f,0.f,0.f,0.f);
  }
  const int lane = tid & 31, grp = tid >> 5;
  const int d0 = lane*4;

  #pragma unroll
  for(int l=0;l<3;l++){
    __syncthreads();
    { // stage W[l]
      const float4* gw = reinterpret_cast<const float4*>(W) + l*4096;
      float4* sW4 = reinterpret_cast<float4*>(sW);
      for(int i=tid;i<4096;i+=128) sW4[i]=gw[i];
    }
    __syncthreads();
    const int R = 2*l+1, m0 = l*l;
    #pragma unroll
    for(int s=0;s<NT/4;s++){
      const int nloc = grp + 4*s;
      const int node = nodeBase + nloc;
      unsigned long long accA[5], accB[5];
      #pragma unroll
      for(int m=0;m<5;m++){ accA[m]=0ULL; accB[m]=0ULL; }
      const float* xrow = sx + (nloc*MTOT + m0)*CCH;
      const ulonglong2* wp = reinterpret_cast<const ulonglong2*>(sW);
      #pragma unroll 4
      for(int c=0;c<CCH;c++){
        ulonglong2 w2 = wp[c*32 + lane];      // W[c, d0..d0+3]
        #pragma unroll
        for(int m=0;m<5;m++){
          if(m < R){
            float xv = xrow[m*CCH + c];       // smem broadcast within warp
            unsigned long long xx;
            asm("mov.b64 %0, {%1, %1};" : "=l"(xx) : "r"(__float_as_uint(xv)));
            asm("fma.rn.f32x2 %0, %1, %2, %0;" : "+l"(accA[m]) : "l"(xx), "l"(w2.x));
            asm("fma.rn.f32x2 %0, %1, %2, %0;" : "+l"(accB[m]) : "l"(xx), "l"(w2.y));
          }
        }
      }
      if(node < N){
        #pragma unroll
        for(int m=0;m<5;m++){
          if(m < R){
            unsigned int u0,u1,u2,u3;
            asm("mov.b64 {%0, %1}, %2;" : "=r"(u0), "=r"(u1) : "l"(accA[m]));
            asm("mov.b64 {%0, %1}, %2;" : "=r"(u2), "=r"(u3) : "l"(accB[m]));
            float v0=__uint_as_float(u0), v1=__uint_as_float(u1);
            float v2=__uint_as_float(u2), v3=__uint_as_float(u3);
            const int mm = m0 + m;
            if(mm==0){ v0+=bias[d0]; v1+=bias[d0+1]; v2+=bias[d0+2]; v3+=bias[d0+3]; }
            if(applyPN){
              float pn = (mm==0) ? 1.0f : ((mm<4) ? 0.57735026918962576f : 0.70710678118654752f);
              v0*=pn; v1*=pn; v2*=pn; v3*=pn;
            }
            reinterpret_cast<float4*>(out)[ ((size_t)node*MTOT + mm)*32 + lane ] =
                make_float4(v0,v1,v2,v3);
          }
        }
      }
    }
  }
}

// ======================================================================
// Kernel 2: source-side tensor product  c2src = tp_uvu(exp_h1, s*exp_pos)
// one thread per (node, channel)
// ======================================================================
__global__ __launch_bounds__(256)
void tp_src_kernel(const float* __restrict__ exp_h1, const float* __restrict__ exp_pos,
                   const float* __restrict__ tp_w, float* __restrict__ c2src,
                   int N2, W3J w, float scale)
{
  const int t = blockIdx.x*blockDim.x + threadIdx.x;
  const int node = t >> 7;
  if(node >= N2) return;
  const int d = t & 127;
  const float* px = exp_h1 + (size_t)node*MTOT*CCH + d;
  float x[MTOT];
  #pragma unroll
  for(int m=0;m<MTOT;m++) x[m] = px[m*CCH];
  float y[3];
  #pragma unroll
  for(int b=0;b<3;b++) y[b] = scale * exp_pos[node*3+b];
  float tpw[6];
  #pragma unroll
  for(int p=0;p<6;p++) tpw[p] = tp_w[p*CCH + d];
  float o[MTOT];
  tp_point(x, y, tpw, w, o);
  float* po = c2src + (size_t)node*MTOT*CCH + d;
  #pragma unroll
  for(int m=0;m<MTOT;m++) po[m*CCH] = o[m];
}

// ======================================================================
// Kernel 3: fused gather + head-weighted aggregation + target-side TP +
// subtraction. 128 threads per target node (thread = channel), 2 targets
// per 256-thread block. L2-resident random gathers dominate.
// ======================================================================
__global__ __launch_bounds__(256)
void gather_kernel(const float* __restrict__ exp_h1, const float* __restrict__ c2src,
                   const float* __restrict__ pos, const float* __restrict__ alpha,
                   const int* __restrict__ idx, const float* __restrict__ tp_w,
                   float* __restrict__ cdiff, int N1, W3J w, float scale)
{
  const int b = blockIdx.x*2 + (threadIdx.x >> 7);
  if(b >= N1) return;
  const int d = threadIdx.x & 127;
  const int h = d >> 4;

  float ax[MTOT], ac[MTOT];
  #pragma unroll
  for(int m=0;m<MTOT;m++){ ax[m]=0.f; ac[m]=0.f; }

  const int*   ib = idx   + (size_t)b*KNB;
  const float* ab = alpha + (size_t)b*KNB*HH;

  #pragma unroll 4
  for(int j=0;j<KNB;j++){
    const int n = ib[j];
    const float a = ab[j*HH + h];
    const float* px = exp_h1 + (size_t)n*MTOT*CCH + d;
    const float* pc = c2src  + (size_t)n*MTOT*CCH + d;
    #pragma unroll
    for(int m=0;m<MTOT;m++){
      ax[m] = fmaf(a, px[m*CCH], ax[m]);
      ac[m] = fmaf(a, pc[m*CCH], ac[m]);
    }
  }

  float y[3];
  #pragma unroll
  for(int t=0;t<3;t++) y[t] = scale * pos[b*3+t];
  float tpw[6];
  #pragma unroll
  for(int p=0;p<6;p++) tpw[p] = tp_w[p*CCH + d];
  float o[MTOT];
  tp_point(ax, y, tpw, w, o);

  float* od = cdiff + (size_t)b*MTOT*CCH + d;
  #pragma unroll
  for(int m=0;m<MTOT;m++) od[m*CCH] = o[m] - ac[m];
}

// ======================================================================
// launch
// ======================================================================
extern "C" void kernel_launch(void* const* d_in, const int* in_sizes, int n_in,
                              void* d_out, int out_size)
{
  const float* pos     = (const float*)d_in[0];
  const float* exp_pos = (const float*)d_in[1];
  // d_in[2] = h : unused by the reference
  const float* exp_h   = (const float*)d_in[3];
  const float* alpha   = (const float*)d_in[4];
  const int*   idx     = (const int*)  d_in[5];
  const float* w1w     = (const float*)d_in[6];
  const float* w1b     = (const float*)d_in[7];
  const float* w2w     = (const float*)d_in[8];
  const float* w2b     = (const float*)d_in[9];
  const float* tpw     = (const float*)d_in[10];

  const int N1 = in_sizes[0]/3;
  const int N2 = in_sizes[1]/3;

  W3J w;
  build_w3j(&w);
  const double PI = 3.14159265358979323846;
  const float scale = (float)(2.04665350914 * std::sqrt(3.0/(4.0*PI)));  // COEF1 * SH1_INT

  float *p_h1=nullptr, *p_c2=nullptr, *p_cd=nullptr;
  cudaGetSymbolAddress((void**)&p_h1, g_exp_h1);
  cudaGetSymbolAddress((void**)&p_c2, g_c2src);
  cudaGetSymbolAddress((void**)&p_cd, g_cdiff);

  const int smemB = (16384 + NT*MTOT*CCH)*4;  // 102400 B
  cudaFuncSetAttribute(so3lin_kernel, cudaFuncAttributeMaxDynamicSharedMemorySize, smemB);

  // 1) exp_h1 = so3_linear(exp_h, w1)
  so3lin_kernel<<<(N2+NT-1)/NT, 128, smemB>>>(exp_h, w1w, w1b, p_h1, N2, 0);
  // 2) c2src = tp_uvu(exp_h1, s*exp_pos)
  tp_src_kernel<<<(N2*CCH + 255)/256, 256>>>(p_h1, exp_pos, tpw, p_c2, N2, w, scale);
  // 3) cdiff = tp_uvu(agg(exp_h1), s*pos) - agg(c2src)
  gather_kernel<<<(N1+1)/2, 256>>>(p_h1, p_c2, pos, alpha, idx, tpw, p_cd, N1, w, scale);
  // 4) out = so3_linear(cdiff, w2) * PATH_NORM
  so3lin_kernel<<<(N1+NT-1)/NT, 128, smemB>>>(p_cd, w2w, w2b, (float*)d_out, N1, 1);
}

// round 3
// speedup vs baseline: 1.6486x; 1.6486x over previous
#include <cuda_runtime.h>
#include <cuda_fp16.h>
#include <cmath>
#include <complex>
#include <algorithm>
#include <cstdint>

// ---------------- problem constants ----------------
#define MTOT 9        // (LMAX+1)^2
#define CCH  128      // channels
#define KNB  16       // neighbors
#define HH   8        // heads
#define MAXN 4096     // max nodes (matches setup)

struct W3J { float v[210]; };   // packed per-path: (0,1)@0:9 (1,0)@9:9 (1,1)@18:27 (1,2)@45:45 (2,1)@90:45 (2,2)@135:75

// ---------------- scratch (static device globals; no allocation) ----------------
__device__ float g_exp_h1[MAXN * MTOT * CCH];
__device__ float g_c2src [MAXN * MTOT * CCH];
__device__ float g_cdiff [MAXN * MTOT * CCH];
__device__ __half g_Whi[2 * 3 * CCH * CCH];   // transposed: [which][l][d_out][c_in]
__device__ __half g_Wlo[2 * 3 * CCH * CCH];

// ======================================================================
// Host-side real Wigner-3j construction (port of the e3nn-style reference)
// ======================================================================
static double hfact(int n){ double r=1.0; for(int i=2;i<=n;i++) r*= (double)i; return r; }

static double su2_cg(int j1,int j2,int j3,int m1,int m2,int m3){
  if(m3 != m1+m2) return 0.0;
  if(j3 < std::abs(j1-j2) || j3 > j1+j2) return 0.0;
  double pref = std::sqrt((2.0*j3+1.0)*hfact(j1+j2-j3)*hfact(j1-j2+j3)*hfact(-j1+j2+j3)/hfact(j1+j2+j3+1));
  pref *= std::sqrt(hfact(j3+m3)*hfact(j3-m3)*hfact(j1-m1)*hfact(j1+m1)*hfact(j2-m2)*hfact(j2+m2));
  int vmin = std::max(0, std::max(j2-j3-m1, j1-j3+m2));
  int vmax = std::min(j1+j2-j3, std::min(j1-m1, j2+m2));
  double s=0.0;
  for(int v=vmin; v<=vmax; v++){
    double den = hfact(v)*hfact(j1+j2-j3-v)*hfact(j1-m1-v)*hfact(j2+m2-v)*hfact(j3-j2+m1+v)*hfact(j3-j1-m2+v);
    s += ((v&1)? -1.0 : 1.0)/den;
  }
  return pref*s;
}

static void q_r2c(int l, std::complex<double>* q){
  int n = 2*l+1;
  for(int i=0;i<n*n;i++) q[i]=std::complex<double>(0.0,0.0);
  double is2 = 1.0/std::sqrt(2.0);
  for(int m=-l;m<0;m++){
    q[(l+m)*n + (l-m)] = std::complex<double>(is2, 0.0);
    q[(l+m)*n + (l+m)] = std::complex<double>(0.0,-is2);
  }
  q[l*n + l] = std::complex<double>(1.0,0.0);
  for(int m=1;m<=l;m++){
    double sg = (m&1)? -1.0 : 1.0;
    q[(l+m)*n + (l+m)] = std::complex<double>(sg*is2, 0.0);
    q[(l+m)*n + (l-m)] = std::complex<double>(0.0, sg*is2);
  }
  std::complex<double> f(1.0,0.0), mi(0.0,-1.0);
  for(int i=0;i<l;i++) f *= mi;
  for(int i=0;i<n*n;i++) q[i] *= f;
}

static void real_w3j(int l1, int l3, float* out){
  const int n1=2*l1+1, n2=3, n3=2*l3+1;
  std::complex<double> Cc[5*3*5];
  for(int i=0;i<n1;i++) for(int j=0;j<n2;j++) for(int k=0;k<n3;k++)
    Cc[(i*n2+j)*n3+k] = std::complex<double>(su2_cg(l1,1,l3, i-l1, j-1, k-l3), 0.0);
  std::complex<double> Q1[25],Q2[9],Q3[25];
  q_r2c(l1,Q1); q_r2c(1,Q2); q_r2c(l3,Q3);
  std::complex<double> C[5*3*5];
  for(int a=0;a<n1;a++) for(int b=0;b<n2;b++) for(int c=0;c<n3;c++){
    std::complex<double> s(0.0,0.0);
    for(int i=0;i<n1;i++) for(int j=0;j<n2;j++) for(int k=0;k<n3;k++)
      s += Q1[i*n1+a]*Q2[j*n2+b]*std::conj(Q3[k*n3+c])*Cc[(i*n2+j)*n3+k];
    C[(a*n2+b)*n3+c]=s;
  }
  double sr=0.0, si=0.0;
  for(int i=0;i<n1*n2*n3;i++){ sr += std::fabs(C[i].real()); si += std::fabs(C[i].imag()); }
  double vals[75]; double norm=0.0;
  for(int i=0;i<n1*n2*n3;i++){ double v=(sr>=si)? C[i].real() : C[i].imag(); vals[i]=v; norm+=v*v; }
  norm = std::sqrt(norm);
  double sc = std::sqrt((double)(2*l3+1))/norm;
  for(int i=0;i<n1*n2*n3;i++) out[i] = (float)(vals[i]*sc);
}

static void build_w3j(W3J* w){
  real_w3j(0,1, w->v+0);
  real_w3j(1,0, w->v+9);
  real_w3j(1,1, w->v+18);
  real_w3j(1,2, w->v+45);
  real_w3j(2,1, w->v+90);
  real_w3j(2,2, w->v+135);
}

// ======================================================================
// Row mapping: GEMM rows grouped by degree.
// rows [0,N): l=0   rows [N,4N): l=1   rows [4N,9N): l=2
// ======================================================================
__device__ __forceinline__ void row_to_nm(int R, int N, int& n, int& m){
  if(R < N){ n = R; m = 0; }
  else if(R < 4*N){ int q = R - N; n = q/3; m = 1 + q%3; }
  else { int q = R - 4*N; n = q/5; m = 4 + q%5; }
}

// ======================================================================
// W conversion: W[l][c][d] fp32 -> transposed split-fp16 Wt[which][l][d][c]
// ======================================================================
__global__ __launch_bounds__(256)
void conv_w_kernel(const float* __restrict__ w1, const float* __restrict__ w2,
                   __half* __restrict__ Whi, __half* __restrict__ Wlo)
{
  int t = blockIdx.x*256 + threadIdx.x;
  if(t >= 2*3*CCH*CCH) return;
  int which = t / (3*CCH*CCH);
  int rem = t % (3*CCH*CCH);
  int l = rem / (CCH*CCH);
  int e = rem % (CCH*CCH);
  int d = e >> 7, c = e & 127;
  const float* w = which ? w2 : w1;
  float v = w[((size_t)l*CCH + c)*CCH + d];
  __half hi = __float2half_rn(v);
  __half lo = __float2half_rn(v - __half2float(hi));
  Whi[t] = hi;
  Wlo[t] = lo;
}

// ======================================================================
// Split-fp16 HMMA GEMM (mma.sync.m16n8k16), fused fp32->fp16 conversion.
// CTA: 64 rows x 128 out-cols, K=128. 4 warps, warp = 16 rows x 128 cols.
// D = Ahi*Whi^T + Alo*Whi^T + Ahi*Wlo^T (fp32 accum).
// ======================================================================
#define PADC 136                       // padded smem row stride in halves
#define OFF_AH 0
#define OFF_AL (64*PADC*2)             // 17408
#define OFF_WH (2*64*PADC*2)           // 34816
#define OFF_WL (OFF_WH + 128*PADC*2)   // 69632
#define OFF_BIAS (OFF_WL + 128*PADC*2) // 104448
#define GEMM_SMEM (OFF_BIAS + 512)     // 104960

__device__ __forceinline__ void mma16816(float* c, const uint32_t* a, const uint32_t* b){
  asm volatile("mma.sync.aligned.m16n8k16.row.col.f32.f16.f16.f32 "
               "{%0,%1,%2,%3}, {%4,%5,%6,%7}, {%8,%9}, {%0,%1,%2,%3};"
               : "+f"(c[0]), "+f"(c[1]), "+f"(c[2]), "+f"(c[3])
               : "r"(a[0]), "r"(a[1]), "r"(a[2]), "r"(a[3]), "r"(b[0]), "r"(b[1]));
}

__global__ __launch_bounds__(128, 2)
void gemm_kernel(const float* __restrict__ x, const __half* __restrict__ Whi,
                 const __half* __restrict__ Wlo, const float* __restrict__ bias,
                 float* __restrict__ out, int N, int applyPN)
{
  extern __shared__ char smem[];
  const int tid = threadIdx.x;
  const int wid = tid >> 5, lane = tid & 31;
  const int tile = blockIdx.x;
  const int rows = 9*N;
  const int t0 = N >> 6, t1 = t0*4;              // group boundaries in 64-row tiles
  const int l = (tile < t0) ? 0 : ((tile < t1) ? 1 : 2);

  // ---- stage A (fp32 -> split fp16, padded) ----
  #pragma unroll
  for(int i=0;i<16;i++){
    int j = tid + i*128;            // 2048 float4 = 64 rows x 32
    int row = j >> 5, col4 = j & 31;
    int R = tile*64 + row;
    float4 v = make_float4(0.f,0.f,0.f,0.f);
    if(R < rows){
      int n, m; row_to_nm(R, N, n, m);
      v = reinterpret_cast<const float4*>(x)[ ((size_t)n*MTOT + m)*32 + col4 ];
    }
    __half h0 = __float2half_rn(v.x), h1 = __float2half_rn(v.y);
    __half h2 = __float2half_rn(v.z), h3 = __float2half_rn(v.w);
    __half l0 = __float2half_rn(v.x - __half2float(h0));
    __half l1 = __float2half_rn(v.y - __half2float(h1));
    __half l2 = __float2half_rn(v.z - __half2float(h2));
    __half l3 = __float2half_rn(v.w - __half2float(h3));
    uint2 hp, lp;
    hp.x = __half_as_ushort(h0) | ((uint32_t)__half_as_ushort(h1) << 16);
    hp.y = __half_as_ushort(h2) | ((uint32_t)__half_as_ushort(h3) << 16);
    lp.x = __half_as_ushort(l0) | ((uint32_t)__half_as_ushort(l1) << 16);
    lp.y = __half_as_ushort(l2) | ((uint32_t)__half_as_ushort(l3) << 16);
    *reinterpret_cast<uint2*>(smem + OFF_AH + row*(PADC*2) + col4*8) = hp;
    *reinterpret_cast<uint2*>(smem + OFF_AL + row*(PADC*2) + col4*8) = lp;
  }
  // ---- stage W[l] (already split fp16, copy with padding) ----
  {
    const int4* sh = reinterpret_cast<const int4*>(Whi + (size_t)l*CCH*CCH);
    const int4* sl = reinterpret_cast<const int4*>(Wlo + (size_t)l*CCH*CCH);
    #pragma unroll
    for(int i=0;i<16;i++){
      int j = tid + i*128;          // 2048 int4 = 128 rows x 16
      int row = j >> 4, chunk = j & 15;
      *reinterpret_cast<int4*>(smem + OFF_WH + row*(PADC*2) + chunk*16) = sh[j];
      *reinterpret_cast<int4*>(smem + OFF_WL + row*(PADC*2) + chunk*16) = sl[j];
    }
  }
  if(tid < 128) *reinterpret_cast<float*>(smem + OFF_BIAS + tid*4) = bias[tid];
  __syncthreads();

  // ---- mainloop ----
  const int g = lane >> 2, t = lane & 3;
  const int arow0 = wid*16 + g;       // A fragment rows: arow0, arow0+8
  float acc[64];
  #pragma unroll
  for(int i=0;i<64;i++) acc[i] = 0.f;

  #pragma unroll
  for(int ks=0; ks<8; ks++){
    const int k0 = ks*16;
    uint32_t aH[4], aL[4];
    aH[0] = *reinterpret_cast<const uint32_t*>(smem + OFF_AH + (arow0  )*(PADC*2) + (k0 + 2*t    )*2);
    aH[1] = *reinterpret_cast<const uint32_t*>(smem + OFF_AH + (arow0+8)*(PADC*2) + (k0 + 2*t    )*2);
    aH[2] = *reinterpret_cast<const uint32_t*>(smem + OFF_AH + (arow0  )*(PADC*2) + (k0 + 2*t + 8)*2);
    aH[3] = *reinterpret_cast<const uint32_t*>(smem + OFF_AH + (arow0+8)*(PADC*2) + (k0 + 2*t + 8)*2);
    aL[0] = *reinterpret_cast<const uint32_t*>(smem + OFF_AL + (arow0  )*(PADC*2) + (k0 + 2*t    )*2);
    aL[1] = *reinterpret_cast<const uint32_t*>(smem + OFF_AL + (arow0+8)*(PADC*2) + (k0 + 2*t    )*2);
    aL[2] = *reinterpret_cast<const uint32_t*>(smem + OFF_AL + (arow0  )*(PADC*2) + (k0 + 2*t + 8)*2);
    aL[3] = *reinterpret_cast<const uint32_t*>(smem + OFF_AL + (arow0+8)*(PADC*2) + (k0 + 2*t + 8)*2);
    #pragma unroll
    for(int nt=0; nt<16; nt++){
      const int brow = nt*8 + g;      // Wt row = output col index
      uint32_t bH[2], bL[2];
      bH[0] = *reinterpret_cast<const uint32_t*>(smem + OFF_WH + brow*(PADC*2) + (k0 + 2*t    )*2);
      bH[1] = *reinterpret_cast<const uint32_t*>(smem + OFF_WH + brow*(PADC*2) + (k0 + 2*t + 8)*2);
      mma16816(acc + nt*4, aH, bH);
      mma16816(acc + nt*4, aL, bH);
      bL[0] = *reinterpret_cast<const uint32_t*>(smem + OFF_WL + brow*(PADC*2) + (k0 + 2*t    )*2);
      bL[1] = *reinterpret_cast<const uint32_t*>(smem + OFF_WL + brow*(PADC*2) + (k0 + 2*t + 8)*2);
      mma16816(acc + nt*4, aH, bL);
    }
  }

  // ---- epilogue: c0=(g,2t) c1=(g,2t+1) c2=(g+8,2t) c3=(g+8,2t+1) per ntile ----
  const float* sbias = reinterpret_cast<const float*>(smem + OFF_BIAS);
  #pragma unroll
  for(int half=0; half<2; half++){
    const int R = tile*64 + arow0 + half*8;
    if(R >= rows) continue;
    int n, m; row_to_nm(R, N, n, m);
    float pn = 1.0f;
    if(applyPN) pn = (m==0) ? 1.0f : ((m<4) ? 0.57735026918962576f : 0.70710678118654752f);
    float* po = out + ((size_t)n*MTOT + m)*CCH;
    #pragma unroll
    for(int nt=0; nt<16; nt++){
      const int c0 = nt*8 + 2*t;
      float v0 = acc[nt*4 + half*2 + 0];
      float v1 = acc[nt*4 + half*2 + 1];
      if(m == 0){ v0 += sbias[c0]; v1 += sbias[c0+1]; }
      v0 *= pn; v1 *= pn;
      *reinterpret_cast<float2*>(po + c0) = make_float2(v0, v1);
    }
  }
}

// ======================================================================
// Device: depthwise uvu tensor product of one (node, channel) point
// ======================================================================
__device__ __forceinline__ void tp_point(const float* x, const float* y, const float* tpw,
                                         const W3J& w, float* o){
  #pragma unroll
  for(int m=0;m<MTOT;m++) o[m]=0.0f;
  float p0[3], p1[9], p2[15];
  #pragma unroll
  for(int b=0;b<3;b++) p0[b] = x[0]*y[b];
  #pragma unroll
  for(int a=0;a<3;a++){
    #pragma unroll
    for(int b=0;b<3;b++) p1[a*3+b] = x[1+a]*y[b];
  }
  #pragma unroll
  for(int a=0;a<5;a++){
    #pragma unroll
    for(int b=0;b<3;b++) p2[a*3+b] = x[4+a]*y[b];
  }
  #pragma unroll
  for(int c=0;c<3;c++){
    float t=0.f;
    #pragma unroll
    for(int b=0;b<3;b++) t = fmaf(w.v[0 + b*3 + c], p0[b], t);
    o[1+c] = fmaf(tpw[0], t, o[1+c]);
  }
  {
    float t=0.f;
    #pragma unroll
    for(int a=0;a<3;a++)
      #pragma unroll
      for(int b=0;b<3;b++) t = fmaf(w.v[9 + a*3 + b], p1[a*3+b], t);
    o[0] = fmaf(tpw[1], t, o[0]);
  }
  #pragma unroll
  for(int c=0;c<3;c++){
    float t=0.f;
    #pragma unroll
    for(int a=0;a<3;a++)
      #pragma unroll
      for(int b=0;b<3;b++) t = fmaf(w.v[18 + (a*3+b)*3 + c], p1[a*3+b], t);
    o[1+c] = fmaf(tpw[2], t, o[1+c]);
  }
  #pragma unroll
  for(int c=0;c<5;c++){
    float t=0.f;
    #pragma unroll
    for(int a=0;a<3;a++)
      #pragma unroll
      for(int b=0;b<3;b++) t = fmaf(w.v[45 + (a*3+b)*5 + c], p1[a*3+b], t);
    o[4+c] = fmaf(tpw[3], t, o[4+c]);
  }
  #pragma unroll
  for(int c=0;c<3;c++){
    float t=0.f;
    #pragma unroll
    for(int a=0;a<5;a++)
      #pragma unroll
      for(int b=0;b<3;b++) t = fmaf(w.v[90 + (a*3+b)*3 + c], p2[a*3+b], t);
    o[1+c] = fmaf(tpw[4], t, o[1+c]);
  }
  #pragma unroll
  for(int c=0;c<5;c++){
    float t=0.f;
    #pragma unroll
    for(int a=0;a<5;a++)
      #pragma unroll
      for(int b=0;b<3;b++) t = fmaf(w.v[135 + (a*3+b)*5 + c], p2[a*3+b], t);
    o[4+c] = fmaf(tpw[5], t, o[4+c]);
  }
}

// ======================================================================
// source-side tensor product  c2src = tp_uvu(exp_h1, s*exp_pos)
// ======================================================================
__global__ __launch_bounds__(256)
void tp_src_kernel(const float* __restrict__ exp_h1, const float* __restrict__ exp_pos,
                   const float* __restrict__ tp_w, float* __restrict__ c2src,
                   int N2, W3J w, float scale)
{
  const int t = blockIdx.x*blockDim.x + threadIdx.x;
  const int node = t >> 7;
  if(node >= N2) return;
  const int d = t & 127;
  const float* px = exp_h1 + (size_t)node*MTOT*CCH + d;
  float x[MTOT];
  #pragma unroll
  for(int m=0;m<MTOT;m++) x[m] = px[m*CCH];
  float y[3];
  #pragma unroll
  for(int b=0;b<3;b++) y[b] = scale * exp_pos[node*3+b];
  float tpw[6];
  #pragma unroll
  for(int p=0;p<6;p++) tpw[p] = tp_w[p*CCH + d];
  float o[MTOT];
  tp_point(x, y, tpw, w, o);
  float* po = c2src + (size_t)node*MTOT*CCH + d;
  #pragma unroll
  for(int m=0;m<MTOT;m++) po[m*CCH] = o[m];
}

// ======================================================================
// fused gather + head-weighted aggregation + target-side TP + subtraction
// ======================================================================
__global__ __launch_bounds__(256)
void gather_kernel(const float* __restrict__ exp_h1, const float* __restrict__ c2src,
                   const float* __restrict__ pos, const float* __restrict__ alpha,
                   const int* __restrict__ idx, const float* __restrict__ tp_w,
                   float* __restrict__ cdiff, int N1, W3J w, float scale)
{
  const int b = blockIdx.x*2 + (threadIdx.x >> 7);
  if(b >= N1) return;
  const int d = threadIdx.x & 127;
  const int h = d >> 4;

  float ax[MTOT], ac[MTOT];
  #pragma unroll
  for(int m=0;m<MTOT;m++){ ax[m]=0.f; ac[m]=0.f; }

  const int*   ib = idx   + (size_t)b*KNB;
  const float* ab = alpha + (size_t)b*KNB*HH;

  #pragma unroll 4
  for(int j=0;j<KNB;j++){
    const int n = ib[j];
    const float a = ab[j*HH + h];
    const float* px = exp_h1 + (size_t)n*MTOT*CCH + d;
    const float* pc = c2src  + (size_t)n*MTOT*CCH + d;
    #pragma unroll
    for(int m=0;m<MTOT;m++){
      ax[m] = fmaf(a, px[m*CCH], ax[m]);
      ac[m] = fmaf(a, pc[m*CCH], ac[m]);
    }
  }

  float y[3];
  #pragma unroll
  for(int t=0;t<3;t++) y[t] = scale * pos[b*3+t];
  float tpw[6];
  #pragma unroll
  for(int p=0;p<6;p++) tpw[p] = tp_w[p*CCH + d];
  float o[MTOT];
  tp_point(ax, y, tpw, w, o);

  float* od = cdiff + (size_t)b*MTOT*CCH + d;
  #pragma unroll
  for(int m=0;m<MTOT;m++) od[m*CCH] = o[m] - ac[m];
}

// ======================================================================
// launch
// ======================================================================
extern "C" void kernel_launch(void* const* d_in, const int* in_sizes, int n_in,
                              void* d_out, int out_size)
{
  const float* pos     = (const float*)d_in[0];
  const float* exp_pos = (const float*)d_in[1];
  // d_in[2] = h : unused by the reference
  const float* exp_h   = (const float*)d_in[3];
  const float* alpha   = (const float*)d_in[4];
  const int*   idx     = (const int*)  d_in[5];
  const float* w1w     = (const float*)d_in[6];
  const float* w1b     = (const float*)d_in[7];
  const float* w2w     = (const float*)d_in[8];
  const float* w2b     = (const float*)d_in[9];
  const float* tpw     = (const float*)d_in[10];

  const int N1 = in_sizes[0]/3;
  const int N2 = in_sizes[1]/3;

  W3J w;
  build_w3j(&w);
  const double PI = 3.14159265358979323846;
  const float scale = (float)(2.04665350914 * std::sqrt(3.0/(4.0*PI)));  // COEF1 * SH1_INT

  float *p_h1=nullptr, *p_c2=nullptr, *p_cd=nullptr;
  __half *p_whi=nullptr, *p_wlo=nullptr;
  cudaGetSymbolAddress((void**)&p_h1,  g_exp_h1);
  cudaGetSymbolAddress((void**)&p_c2,  g_c2src);
  cudaGetSymbolAddress((void**)&p_cd,  g_cdiff);
  cudaGetSymbolAddress((void**)&p_whi, g_Whi);
  cudaGetSymbolAddress((void**)&p_wlo, g_Wlo);

  cudaFuncSetAttribute(gemm_kernel, cudaFuncAttributeMaxDynamicSharedMemorySize, GEMM_SMEM);

  const int tiles2 = (9*N2 + 63) >> 6;   // 576 for N2=4096
  const int tiles1 = (9*N1 + 63) >> 6;

  // 0) W images (both linears, hi/lo, transposed)
  conv_w_kernel<<<(2*3*CCH*CCH + 255)/256, 256>>>(w1w, w2w, p_whi, p_wlo);
  // 1) exp_h1 = so3_linear(exp_h, w1)   [fused conversion + HMMA GEMM]
  gemm_kernel<<<tiles2, 128, GEMM_SMEM>>>(exp_h, p_whi, p_wlo, w1b, p_h1, N2, 0);
  // 2) c2src = tp_uvu(exp_h1, s*exp_pos)
  tp_src_kernel<<<(N2*CCH + 255)/256, 256>>>(p_h1, exp_pos, tpw, p_c2, N2, w, scale);
  // 3) cdiff = tp_uvu(agg(exp_h1), s*pos) - agg(c2src)
  gather_kernel<<<(N1+1)/2, 256>>>(p_h1, p_c2, pos, alpha, idx, tpw, p_cd, N1, w, scale);
  // 4) out = so3_linear(cdiff, w2) * PATH_NORM
  gemm_kernel<<<tiles1, 128, GEMM_SMEM>>>(p_cd, p_whi + 3*CCH*CCH, p_wlo + 3*CCH*CCH,
                                          w2b, (float*)d_out, N1, 1);
}

// round 4
// speedup vs baseline: 1.7441x; 1.0579x over previous
#include <cuda_runtime.h>
#include <cuda_fp16.h>
#include <cmath>
#include <complex>
#include <algorithm>
#include <cstdint>

// ---------------- problem constants ----------------
#define MTOT 9        // (LMAX+1)^2
#define CCH  128      // channels
#define KNB  16       // neighbors
#define HH   8        // heads
#define MAXN 4096     // max nodes (matches setup)

struct W3J { float v[210]; };   // packed per-path: (0,1)@0:9 (1,0)@9:9 (1,1)@18:27 (1,2)@45:45 (2,1)@90:45 (2,2)@135:75

// ---------------- scratch (static device globals; no allocation) ----------------
__device__ float  g_exp_h1[MAXN * MTOT * CCH];     // fp32 master (for tp_src)
__device__ float  g_cdiff [MAXN * MTOT * CCH];
__device__ __half g_h1f16 [MAXN * MTOT * CCH];     // fp16 gather payloads
__device__ __half g_c2f16 [MAXN * MTOT * CCH];
__device__ __half g_Whi[2 * 3 * CCH * CCH];        // transposed: [which][l][d_out][c_in]
__device__ __half g_Wlo[2 * 3 * CCH * CCH];

// ======================================================================
// Host-side real Wigner-3j construction (port of the e3nn-style reference)
// ======================================================================
static double hfact(int n){ double r=1.0; for(int i=2;i<=n;i++) r*= (double)i; return r; }

static double su2_cg(int j1,int j2,int j3,int m1,int m2,int m3){
  if(m3 != m1+m2) return 0.0;
  if(j3 < std::abs(j1-j2) || j3 > j1+j2) return 0.0;
  double pref = std::sqrt((2.0*j3+1.0)*hfact(j1+j2-j3)*hfact(j1-j2+j3)*hfact(-j1+j2+j3)/hfact(j1+j2+j3+1));
  pref *= std::sqrt(hfact(j3+m3)*hfact(j3-m3)*hfact(j1-m1)*hfact(j1+m1)*hfact(j2-m2)*hfact(j2+m2));
  int vmin = std::max(0, std::max(j2-j3-m1, j1-j3+m2));
  int vmax = std::min(j1+j2-j3, std::min(j1-m1, j2+m2));
  double s=0.0;
  for(int v=vmin; v<=vmax; v++){
    double den = hfact(v)*hfact(j1+j2-j3-v)*hfact(j1-m1-v)*hfact(j2+m2-v)*hfact(j3-j2+m1+v)*hfact(j3-j1-m2+v);
    s += ((v&1)? -1.0 : 1.0)/den;
  }
  return pref*s;
}

static void q_r2c(int l, std::complex<double>* q){
  int n = 2*l+1;
  for(int i=0;i<n*n;i++) q[i]=std::complex<double>(0.0,0.0);
  double is2 = 1.0/std::sqrt(2.0);
  for(int m=-l;m<0;m++){
    q[(l+m)*n + (l-m)] = std::complex<double>(is2, 0.0);
    q[(l+m)*n + (l+m)] = std::complex<double>(0.0,-is2);
  }
  q[l*n + l] = std::complex<double>(1.0,0.0);
  for(int m=1;m<=l;m++){
    double sg = (m&1)? -1.0 : 1.0;
    q[(l+m)*n + (l+m)] = std::complex<double>(sg*is2, 0.0);
    q[(l+m)*n + (l-m)] = std::complex<double>(0.0, sg*is2);
  }
  std::complex<double> f(1.0,0.0), mi(0.0,-1.0);
  for(int i=0;i<l;i++) f *= mi;
  for(int i=0;i<n*n;i++) q[i] *= f;
}

static void real_w3j(int l1, int l3, float* out){
  const int n1=2*l1+1, n2=3, n3=2*l3+1;
  std::complex<double> Cc[5*3*5];
  for(int i=0;i<n1;i++) for(int j=0;j<n2;j++) for(int k=0;k<n3;k++)
    Cc[(i*n2+j)*n3+k] = std::complex<double>(su2_cg(l1,1,l3, i-l1, j-1, k-l3), 0.0);
  std::complex<double> Q1[25],Q2[9],Q3[25];
  q_r2c(l1,Q1); q_r2c(1,Q2); q_r2c(l3,Q3);
  std::complex<double> C[5*3*5];
  for(int a=0;a<n1;a++) for(int b=0;b<n2;b++) for(int c=0;c<n3;c++){
    std::complex<double> s(0.0,0.0);
    for(int i=0;i<n1;i++) for(int j=0;j<n2;j++) for(int k=0;k<n3;k++)
      s += Q1[i*n1+a]*Q2[j*n2+b]*std::conj(Q3[k*n3+c])*Cc[(i*n2+j)*n3+k];
    C[(a*n2+b)*n3+c]=s;
  }
  double sr=0.0, si=0.0;
  for(int i=0;i<n1*n2*n3;i++){ sr += std::fabs(C[i].real()); si += std::fabs(C[i].imag()); }
  double vals[75]; double norm=0.0;
  for(int i=0;i<n1*n2*n3;i++){ double v=(sr>=si)? C[i].real() : C[i].imag(); vals[i]=v; norm+=v*v; }
  norm = std::sqrt(norm);
  double sc = std::sqrt((double)(2*l3+1))/norm;
  for(int i=0;i<n1*n2*n3;i++) out[i] = (float)(vals[i]*sc);
}

static void build_w3j(W3J* w){
  real_w3j(0,1, w->v+0);
  real_w3j(1,0, w->v+9);
  real_w3j(1,1, w->v+18);
  real_w3j(1,2, w->v+45);
  real_w3j(2,1, w->v+90);
  real_w3j(2,2, w->v+135);
}

// ======================================================================
// Row mapping: GEMM rows grouped by degree.
// ======================================================================
__device__ __forceinline__ void row_to_nm(int R, int N, int& n, int& m){
  if(R < N){ n = R; m = 0; }
  else if(R < 4*N){ int q = R - N; n = q/3; m = 1 + q%3; }
  else { int q = R - 4*N; n = q/5; m = 4 + q%5; }
}

// ======================================================================
// W conversion: W[l][c][d] fp32 -> transposed split-fp16 Wt[which][l][d][c]
// ======================================================================
__global__ __launch_bounds__(256)
void conv_w_kernel(const float* __restrict__ w1, const float* __restrict__ w2,
                   __half* __restrict__ Whi, __half* __restrict__ Wlo)
{
  int t = blockIdx.x*256 + threadIdx.x;
  if(t >= 2*3*CCH*CCH) return;
  int which = t / (3*CCH*CCH);
  int rem = t % (3*CCH*CCH);
  int l = rem / (CCH*CCH);
  int e = rem % (CCH*CCH);
  int d = e >> 7, c = e & 127;
  const float* w = which ? w2 : w1;
  float v = w[((size_t)l*CCH + c)*CCH + d];
  __half hi = __float2half_rn(v);
  __half lo = __float2half_rn(v - __half2float(hi));
  Whi[t] = hi;
  Wlo[t] = lo;
}

// ======================================================================
// Split-fp16 HMMA GEMM (mma.sync.m16n8k16), fused fp32->fp16 conversion.
// CTA: 128 rows x 128 out-cols, K=128. 8 warps, warp = 16 rows x 128 cols.
// D = Ahi*Whi^T + Alo*Whi^T + Ahi*Wlo^T (fp32 accum).
// ======================================================================
#define PADC 136                        // padded smem row stride in halves
#define OFF_AH 0
#define OFF_AL (128*PADC*2)             // 34816
#define OFF_WH (2*128*PADC*2)           // 69632
#define OFF_WL (OFF_WH + 128*PADC*2)    // 104448
#define OFF_BIAS (OFF_WL + 128*PADC*2)  // 139264
#define GEMM_SMEM (OFF_BIAS + 512)      // 139776

__device__ __forceinline__ void mma16816(float* c, const uint32_t* a, const uint32_t* b){
  asm volatile("mma.sync.aligned.m16n8k16.row.col.f32.f16.f16.f32 "
               "{%0,%1,%2,%3}, {%4,%5,%6,%7}, {%8,%9}, {%0,%1,%2,%3};"
               : "+f"(c[0]), "+f"(c[1]), "+f"(c[2]), "+f"(c[3])
               : "r"(a[0]), "r"(a[1]), "r"(a[2]), "r"(a[3]), "r"(b[0]), "r"(b[1]));
}

__global__ __launch_bounds__(256, 1)
void gemm_kernel(const float* __restrict__ x, const __half* __restrict__ Whi,
                 const __half* __restrict__ Wlo, const float* __restrict__ bias,
                 float* __restrict__ out, __half* __restrict__ out16,
                 int N, int applyPN)
{
  extern __shared__ char smem[];
  const int tid = threadIdx.x;
  const int wid = tid >> 5, lane = tid & 31;
  const int tile = blockIdx.x;
  const int rows = 9*N;
  const int t0 = N >> 7, t1 = t0*4;              // group boundaries in 128-row tiles
  const int l = (tile < t0) ? 0 : ((tile < t1) ? 1 : 2);

  // ---- stage A (fp32 -> split fp16, padded) ----
  #pragma unroll
  for(int i=0;i<16;i++){
    int j = tid + i*256;            // 4096 float4 = 128 rows x 32
    int row = j >> 5, col4 = j & 31;
    int R = tile*128 + row;
    float4 v = make_float4(0.f,0.f,0.f,0.f);
    if(R < rows){
      int n, m; row_to_nm(R, N, n, m);
      v = reinterpret_cast<const float4*>(x)[ ((size_t)n*MTOT + m)*32 + col4 ];
    }
    __half h0 = __float2half_rn(v.x), h1 = __float2half_rn(v.y);
    __half h2 = __float2half_rn(v.z), h3 = __float2half_rn(v.w);
    __half l0 = __float2half_rn(v.x - __half2float(h0));
    __half l1 = __float2half_rn(v.y - __half2float(h1));
    __half l2 = __float2half_rn(v.z - __half2float(h2));
    __half l3 = __float2half_rn(v.w - __half2float(h3));
    uint2 hp, lp;
    hp.x = __half_as_ushort(h0) | ((uint32_t)__half_as_ushort(h1) << 16);
    hp.y = __half_as_ushort(h2) | ((uint32_t)__half_as_ushort(h3) << 16);
    lp.x = __half_as_ushort(l0) | ((uint32_t)__half_as_ushort(l1) << 16);
    lp.y = __half_as_ushort(l2) | ((uint32_t)__half_as_ushort(l3) << 16);
    *reinterpret_cast<uint2*>(smem + OFF_AH + row*(PADC*2) + col4*8) = hp;
    *reinterpret_cast<uint2*>(smem + OFF_AL + row*(PADC*2) + col4*8) = lp;
  }
  // ---- stage W[l] (already split fp16, copy with padding) ----
  {
    const int4* sh = reinterpret_cast<const int4*>(Whi + (size_t)l*CCH*CCH);
    const int4* sl = reinterpret_cast<const int4*>(Wlo + (size_t)l*CCH*CCH);
    #pragma unroll
    for(int i=0;i<8;i++){
      int j = tid + i*256;          // 2048 int4 = 128 rows x 16
      int row = j >> 4, chunk = j & 15;
      *reinterpret_cast<int4*>(smem + OFF_WH + row*(PADC*2) + chunk*16) = sh[j];
      *reinterpret_cast<int4*>(smem + OFF_WL + row*(PADC*2) + chunk*16) = sl[j];
    }
  }
  if(tid < 128) *reinterpret_cast<float*>(smem + OFF_BIAS + tid*4) = bias[tid];
  __syncthreads();

  // ---- mainloop ----
  const int g = lane >> 2, t = lane & 3;
  const int arow0 = wid*16 + g;       // A fragment rows: arow0, arow0+8
  float acc[64];
  #pragma unroll
  for(int i=0;i<64;i++) acc[i] = 0.f;

  #pragma unroll
  for(int ks=0; ks<8; ks++){
    const int k0 = ks*16;
    uint32_t aH[4], aL[4];
    aH[0] = *reinterpret_cast<const uint32_t*>(smem + OFF_AH + (arow0  )*(PADC*2) + (k0 + 2*t    )*2);
    aH[1] = *reinterpret_cast<const uint32_t*>(smem + OFF_AH + (arow0+8)*(PADC*2) + (k0 + 2*t    )*2);
    aH[2] = *reinterpret_cast<const uint32_t*>(smem + OFF_AH + (arow0  )*(PADC*2) + (k0 + 2*t + 8)*2);
    aH[3] = *reinterpret_cast<const uint32_t*>(smem + OFF_AH + (arow0+8)*(PADC*2) + (k0 + 2*t + 8)*2);
    aL[0] = *reinterpret_cast<const uint32_t*>(smem + OFF_AL + (arow0  )*(PADC*2) + (k0 + 2*t    )*2);
    aL[1] = *reinterpret_cast<const uint32_t*>(smem + OFF_AL + (arow0+8)*(PADC*2) + (k0 + 2*t    )*2);
    aL[2] = *reinterpret_cast<const uint32_t*>(smem + OFF_AL + (arow0  )*(PADC*2) + (k0 + 2*t + 8)*2);
    aL[3] = *reinterpret_cast<const uint32_t*>(smem + OFF_AL + (arow0+8)*(PADC*2) + (k0 + 2*t + 8)*2);
    #pragma unroll
    for(int nt=0; nt<16; nt++){
      const int brow = nt*8 + g;      // Wt row = output col index
      uint32_t bH[2], bL[2];
      bH[0] = *reinterpret_cast<const uint32_t*>(smem + OFF_WH + brow*(PADC*2) + (k0 + 2*t    )*2);
      bH[1] = *reinterpret_cast<const uint32_t*>(smem + OFF_WH + brow*(PADC*2) + (k0 + 2*t + 8)*2);
      mma16816(acc + nt*4, aH, bH);
      mma16816(acc + nt*4, aL, bH);
      bL[0] = *reinterpret_cast<const uint32_t*>(smem + OFF_WL + brow*(PADC*2) + (k0 + 2*t    )*2);
      bL[1] = *reinterpret_cast<const uint32_t*>(smem + OFF_WL + brow*(PADC*2) + (k0 + 2*t + 8)*2);
      mma16816(acc + nt*4, aH, bL);
    }
  }

  // ---- epilogue ----
  const float* sbias = reinterpret_cast<const float*>(smem + OFF_BIAS);
  #pragma unroll
  for(int half=0; half<2; half++){
    const int R = tile*128 + arow0 + half*8;
    if(R >= rows) continue;
    int n, m; row_to_nm(R, N, n, m);
    float pn = 1.0f;
    if(applyPN) pn = (m==0) ? 1.0f : ((m<4) ? 0.57735026918962576f : 0.70710678118654752f);
    float* po = out + ((size_t)n*MTOT + m)*CCH;
    __half2* po16 = out16 ? reinterpret_cast<__half2*>(out16 + ((size_t)n*MTOT + m)*CCH) : nullptr;
    #pragma unroll
    for(int nt=0; nt<16; nt++){
      const int c0 = nt*8 + 2*t;
      float v0 = acc[nt*4 + half*2 + 0];
      float v1 = acc[nt*4 + half*2 + 1];
      if(m == 0){ v0 += sbias[c0]; v1 += sbias[c0+1]; }
      v0 *= pn; v1 *= pn;
      *reinterpret_cast<float2*>(po + c0) = make_float2(v0, v1);
      if(po16) po16[c0 >> 1] = __floats2half2_rn(v0, v1);
    }
  }
}

// ======================================================================
// Device: depthwise uvu tensor product of one (node, channel) point
// ======================================================================
__device__ __forceinline__ void tp_point(const float* x, const float* y, const float* tpw,
                                         const W3J& w, float* o){
  #pragma unroll
  for(int m=0;m<MTOT;m++) o[m]=0.0f;
  float p0[3], p1[9], p2[15];
  #pragma unroll
  for(int b=0;b<3;b++) p0[b] = x[0]*y[b];
  #pragma unroll
  for(int a=0;a<3;a++){
    #pragma unroll
    for(int b=0;b<3;b++) p1[a*3+b] = x[1+a]*y[b];
  }
  #pragma unroll
  for(int a=0;a<5;a++){
    #pragma unroll
    for(int b=0;b<3;b++) p2[a*3+b] = x[4+a]*y[b];
  }
  #pragma unroll
  for(int c=0;c<3;c++){
    float t=0.f;
    #pragma unroll
    for(int b=0;b<3;b++) t = fmaf(w.v[0 + b*3 + c], p0[b], t);
    o[1+c] = fmaf(tpw[0], t, o[1+c]);
  }
  {
    float t=0.f;
    #pragma unroll
    for(int a=0;a<3;a++)
      #pragma unroll
      for(int b=0;b<3;b++) t = fmaf(w.v[9 + a*3 + b], p1[a*3+b], t);
    o[0] = fmaf(tpw[1], t, o[0]);
  }
  #pragma unroll
  for(int c=0;c<3;c++){
    float t=0.f;
    #pragma unroll
    for(int a=0;a<3;a++)
      #pragma unroll
      for(int b=0;b<3;b++) t = fmaf(w.v[18 + (a*3+b)*3 + c], p1[a*3+b], t);
    o[1+c] = fmaf(tpw[2], t, o[1+c]);
  }
  #pragma unroll
  for(int c=0;c<5;c++){
    float t=0.f;
    #pragma unroll
    for(int a=0;a<3;a++)
      #pragma unroll
      for(int b=0;b<3;b++) t = fmaf(w.v[45 + (a*3+b)*5 + c], p1[a*3+b], t);
    o[4+c] = fmaf(tpw[3], t, o[4+c]);
  }
  #pragma unroll
  for(int c=0;c<3;c++){
    float t=0.f;
    #pragma unroll
    for(int a=0;a<5;a++)
      #pragma unroll
      for(int b=0;b<3;b++) t = fmaf(w.v[90 + (a*3+b)*3 + c], p2[a*3+b], t);
    o[1+c] = fmaf(tpw[4], t, o[1+c]);
  }
  #pragma unroll
  for(int c=0;c<5;c++){
    float t=0.f;
    #pragma unroll
    for(int a=0;a<5;a++)
      #pragma unroll
      for(int b=0;b<3;b++) t = fmaf(w.v[135 + (a*3+b)*5 + c], p2[a*3+b], t);
    o[4+c] = fmaf(tpw[5], t, o[4+c]);
  }
}

// ======================================================================
// source-side tensor product: c2f16 = fp16( tp_uvu(exp_h1, s*exp_pos) )
// 2 channels per thread, 64 threads/node, 4 nodes per 256-thread block
// ======================================================================
__global__ __launch_bounds__(256)
void tp_src_kernel(const float* __restrict__ exp_h1, const float* __restrict__ exp_pos,
                   const float* __restrict__ tp_w, __half* __restrict__ c2f16,
                   int N2, W3J w, float scale)
{
  const int node = blockIdx.x*4 + (threadIdx.x >> 6);
  if(node >= N2) return;
  const int t = threadIdx.x & 63;
  const int c0 = 2*t;
  const float* px = exp_h1 + (size_t)node*MTOT*CCH + c0;
  float x0[MTOT], x1[MTOT];
  #pragma unroll
  for(int m=0;m<MTOT;m++){
    float2 v = *reinterpret_cast<const float2*>(px + m*CCH);
    x0[m] = v.x; x1[m] = v.y;
  }
  float y[3];
  #pragma unroll
  for(int b=0;b<3;b++) y[b] = scale * exp_pos[node*3+b];
  float tpw0[6], tpw1[6];
  #pragma unroll
  for(int p=0;p<6;p++){
    float2 v = *reinterpret_cast<const float2*>(tp_w + p*CCH + c0);
    tpw0[p] = v.x; tpw1[p] = v.y;
  }
  float o0[MTOT], o1[MTOT];
  tp_point(x0, y, tpw0, w, o0);
  tp_point(x1, y, tpw1, w, o1);
  __half2* po = reinterpret_cast<__half2*>(c2f16 + (size_t)node*MTOT*CCH) + t;
  #pragma unroll
  for(int m=0;m<MTOT;m++) po[m*64] = __floats2half2_rn(o0[m], o1[m]);
}

// ======================================================================
// fused gather + head-weighted aggregation + target-side TP + subtraction
// fp16 payloads, 2 channels/thread (half2), 64 threads/node, 4 nodes/block
// ======================================================================
__global__ __launch_bounds__(256)
void gather_kernel(const __half* __restrict__ h1f, const __half* __restrict__ c2f,
                   const float* __restrict__ pos, const float* __restrict__ alpha,
                   const int* __restrict__ idx, const float* __restrict__ tp_w,
                   float* __restrict__ cdiff, int N1, W3J w, float scale)
{
  const int b = blockIdx.x*4 + (threadIdx.x >> 6);
  if(b >= N1) return;
  const int t = threadIdx.x & 63;
  const int c0 = 2*t;
  const int h = c0 >> 4;

  float2 ax[MTOT], ac[MTOT];
  #pragma unroll
  for(int m=0;m<MTOT;m++){ ax[m]=make_float2(0.f,0.f); ac[m]=make_float2(0.f,0.f); }

  const int*   ib = idx   + (size_t)b*KNB;
  const float* ab = alpha + (size_t)b*KNB*HH;

  #pragma unroll 4
  for(int j=0;j<KNB;j++){
    const int n = ib[j];
    const float a = ab[j*HH + h];
    const __half2* px = reinterpret_cast<const __half2*>(h1f + (size_t)n*MTOT*CCH) + t;
    const __half2* pc = reinterpret_cast<const __half2*>(c2f + (size_t)n*MTOT*CCH) + t;
    #pragma unroll
    for(int m=0;m<MTOT;m++){
      float2 vx = __half22float2(px[m*64]);
      float2 vc = __half22float2(pc[m*64]);
      ax[m].x = fmaf(a, vx.x, ax[m].x);  ax[m].y = fmaf(a, vx.y, ax[m].y);
      ac[m].x = fmaf(a, vc.x, ac[m].x);  ac[m].y = fmaf(a, vc.y, ac[m].y);
    }
  }

  float y[3];
  #pragma unroll
  for(int k=0;k<3;k++) y[k] = scale * pos[b*3+k];
  float tpw0[6], tpw1[6];
  #pragma unroll
  for(int p=0;p<6;p++){
    float2 v = *reinterpret_cast<const float2*>(tp_w + p*CCH + c0);
    tpw0[p] = v.x; tpw1[p] = v.y;
  }
  float x0[MTOT], x1[MTOT];
  #pragma unroll
  for(int m=0;m<MTOT;m++){ x0[m]=ax[m].x; x1[m]=ax[m].y; }
  float o0[MTOT], o1[MTOT];
  tp_point(x0, y, tpw0, w, o0);
  tp_point(x1, y, tpw1, w, o1);

  float* od = cdiff + (size_t)b*MTOT*CCH + c0;
  #pragma unroll
  for(int m=0;m<MTOT;m++)
    *reinterpret_cast<float2*>(od + m*CCH) = make_float2(o0[m]-ac[m].x, o1[m]-ac[m].y);
}

// ======================================================================
// launch
// ======================================================================
extern "C" void kernel_launch(void* const* d_in, const int* in_sizes, int n_in,
                              void* d_out, int out_size)
{
  const float* pos     = (const float*)d_in[0];
  const float* exp_pos = (const float*)d_in[1];
  // d_in[2] = h : unused by the reference
  const float* exp_h   = (const float*)d_in[3];
  const float* alpha   = (const float*)d_in[4];
  const int*   idx     = (const int*)  d_in[5];
  const float* w1w     = (const float*)d_in[6];
  const float* w1b     = (const float*)d_in[7];
  const float* w2w     = (const float*)d_in[8];
  const float* w2b     = (const float*)d_in[9];
  const float* tpw     = (const float*)d_in[10];

  const int N1 = in_sizes[0]/3;
  const int N2 = in_sizes[1]/3;

  W3J w;
  build_w3j(&w);
  const double PI = 3.14159265358979323846;
  const float scale = (float)(2.04665350914 * std::sqrt(3.0/(4.0*PI)));  // COEF1 * SH1_INT

  float *p_h1=nullptr, *p_cd=nullptr;
  __half *p_h1f=nullptr, *p_c2f=nullptr, *p_whi=nullptr, *p_wlo=nullptr;
  cudaGetSymbolAddress((void**)&p_h1,  g_exp_h1);
  cudaGetSymbolAddress((void**)&p_cd,  g_cdiff);
  cudaGetSymbolAddress((void**)&p_h1f, g_h1f16);
  cudaGetSymbolAddress((void**)&p_c2f, g_c2f16);
  cudaGetSymbolAddress((void**)&p_whi, g_Whi);
  cudaGetSymbolAddress((void**)&p_wlo, g_Wlo);

  cudaFuncSetAttribute(gemm_kernel, cudaFuncAttributeMaxDynamicSharedMemorySize, GEMM_SMEM);

  const int tiles2 = (9*N2 + 127) >> 7;   // 288 for N2=4096
  const int tiles1 = (9*N1 + 127) >> 7;

  // 0) W images (both linears, hi/lo, transposed)
  conv_w_kernel<<<(2*3*CCH*CCH + 255)/256, 256>>>(w1w, w2w, p_whi, p_wlo);
  // 1) exp_h1 = so3_linear(exp_h, w1)  [+ fused fp16 copy for gather]
  gemm_kernel<<<tiles2, 256, GEMM_SMEM>>>(exp_h, p_whi, p_wlo, w1b, p_h1, p_h1f, N2, 0);
  // 2) c2f16 = fp16( tp_uvu(exp_h1, s*exp_pos) )
  tp_src_kernel<<<(N2+3)/4, 256>>>(p_h1, exp_pos, tpw, p_c2f, N2, w, scale);
  // 3) cdiff = tp_uvu(agg(h1f16), s*pos) - agg(c2f16)
  gather_kernel<<<(N1+3)/4, 256>>>(p_h1f, p_c2f, pos, alpha, idx, tpw, p_cd, N1, w, scale);
  // 4) out = so3_linear(cdiff, w2) * PATH_NORM
  gemm_kernel<<<tiles1, 256, GEMM_SMEM>>>(p_cd, p_whi + 3*CCH*CCH, p_wlo + 3*CCH*CCH,
                                          w2b, (float*)d_out, nullptr, N1, 1);
}

// round 6
// speedup vs baseline: 2.3107x; 1.3248x over previous
#include <cuda_runtime.h>
#include <cuda_fp16.h>
#include <cmath>
#include <complex>
#include <algorithm>
#include <cstdint>

// ---------------- problem constants ----------------
#define MTOT 9        // (LMAX+1)^2
#define CCH  128      // channels
#define KNB  16       // neighbors
#define HH   8        // heads
#define MAXN 4096     // max nodes (matches setup)

struct W3J { float v[210]; };   // packed per-path: (0,1)@0:9 (1,0)@9:9 (1,1)@18:27 (1,2)@45:45 (2,1)@90:45 (2,2)@135:75

// ---------------- scratch (static device globals; no allocation) ----------------
__device__ float  g_cdiff [MAXN * MTOT * CCH];
__device__ __half g_h1f16 [MAXN * MTOT * CCH];     // fp16 gather payload
__device__ __half g_Whi[2 * 3 * CCH * CCH];        // transposed: [which][l][d_out][c_in]
__device__ __half g_Wlo[2 * 3 * CCH * CCH];

// ======================================================================
// Host-side real Wigner-3j construction (port of the e3nn-style reference)
// ======================================================================
static double hfact(int n){ double r=1.0; for(int i=2;i<=n;i++) r*= (double)i; return r; }

static double su2_cg(int j1,int j2,int j3,int m1,int m2,int m3){
  if(m3 != m1+m2) return 0.0;
  if(j3 < std::abs(j1-j2) || j3 > j1+j2) return 0.0;
  double pref = std::sqrt((2.0*j3+1.0)*hfact(j1+j2-j3)*hfact(j1-j2+j3)*hfact(-j1+j2+j3)/hfact(j1+j2+j3+1));
  pref *= std::sqrt(hfact(j3+m3)*hfact(j3-m3)*hfact(j1-m1)*hfact(j1+m1)*hfact(j2-m2)*hfact(j2+m2));
  int vmin = std::max(0, std::max(j2-j3-m1, j1-j3+m2));
  int vmax = std::min(j1+j2-j3, std::min(j1-m1, j2+m2));
  double s=0.0;
  for(int v=vmin; v<=vmax; v++){
    double den = hfact(v)*hfact(j1+j2-j3-v)*hfact(j1-m1-v)*hfact(j2+m2-v)*hfact(j3-j2+m1+v)*hfact(j3-j1-m2+v);
    s += ((v&1)? -1.0 : 1.0)/den;
  }
  return pref*s;
}

static void q_r2c(int l, std::complex<double>* q){
  int n = 2*l+1;
  for(int i=0;i<n*n;i++) q[i]=std::complex<double>(0.0,0.0);
  double is2 = 1.0/std::sqrt(2.0);
  for(int m=-l;m<0;m++){
    q[(l+m)*n + (l-m)] = std::complex<double>(is2, 0.0);
    q[(l+m)*n + (l+m)] = std::complex<double>(0.0,-is2);
  }
  q[l*n + l] = std::complex<double>(1.0,0.0);
  for(int m=1;m<=l;m++){
    double sg = (m&1)? -1.0 : 1.0;
    q[(l+m)*n + (l+m)] = std::complex<double>(sg*is2, 0.0);
    q[(l+m)*n + (l-m)] = std::complex<double>(0.0, sg*is2);
  }
  std::complex<double> f(1.0,0.0), mi(0.0,-1.0);
  for(int i=0;i<l;i++) f *= mi;
  for(int i=0;i<n*n;i++) q[i] *= f;
}

static void real_w3j(int l1, int l3, float* out){
  const int n1=2*l1+1, n2=3, n3=2*l3+1;
  std::complex<double> Cc[5*3*5];
  for(int i=0;i<n1;i++) for(int j=0;j<n2;j++) for(int k=0;k<n3;k++)
    Cc[(i*n2+j)*n3+k] = std::complex<double>(su2_cg(l1,1,l3, i-l1, j-1, k-l3), 0.0);
  std::complex<double> Q1[25],Q2[9],Q3[25];
  q_r2c(l1,Q1); q_r2c(1,Q2); q_r2c(l3,Q3);
  std::complex<double> C[5*3*5];
  for(int a=0;a<n1;a++) for(int b=0;b<n2;b++) for(int c=0;c<n3;c++){
    std::complex<double> s(0.0,0.0);
    for(int i=0;i<n1;i++) for(int j=0;j<n2;j++) for(int k=0;k<n3;k++)
      s += Q1[i*n1+a]*Q2[j*n2+b]*std::conj(Q3[k*n3+c])*Cc[(i*n2+j)*n3+k];
    C[(a*n2+b)*n3+c]=s;
  }
  double sr=0.0, si=0.0;
  for(int i=0;i<n1*n2*n3;i++){ sr += std::fabs(C[i].real()); si += std::fabs(C[i].imag()); }
  double vals[75]; double norm=0.0;
  for(int i=0;i<n1*n2*n3;i++){ double v=(sr>=si)? C[i].real() : C[i].imag(); vals[i]=v; norm+=v*v; }
  norm = std::sqrt(norm);
  double sc = std::sqrt((double)(2*l3+1))/norm;
  for(int i=0;i<n1*n2*n3;i++) out[i] = (float)(vals[i]*sc);
}

static void build_w3j(W3J* w){
  real_w3j(0,1, w->v+0);
  real_w3j(1,0, w->v+9);
  real_w3j(1,1, w->v+18);
  real_w3j(1,2, w->v+45);
  real_w3j(2,1, w->v+90);
  real_w3j(2,2, w->v+135);
}

// ======================================================================
// Row mapping: GEMM rows grouped by degree.
// ======================================================================
__device__ __forceinline__ void row_to_nm(int R, int N, int& n, int& m){
  if(R < N){ n = R; m = 0; }
  else if(R < 4*N){ int q = R - N; n = q/3; m = 1 + q%3; }
  else { int q = R - 4*N; n = q/5; m = 4 + q%5; }
}

// ======================================================================
// W conversion: W[l][c][d] fp32 -> transposed split-fp16 Wt[which][l][d][c]
// ======================================================================
__global__ __launch_bounds__(256)
void conv_w_kernel(const float* __restrict__ w1, const float* __restrict__ w2,
                   __half* __restrict__ Whi, __half* __restrict__ Wlo)
{
  int t = blockIdx.x*256 + threadIdx.x;
  if(t >= 2*3*CCH*CCH) return;
  int which = t / (3*CCH*CCH);
  int rem = t % (3*CCH*CCH);
  int l = rem / (CCH*CCH);
  int e = rem % (CCH*CCH);
  int d = e >> 7, c = e & 127;
  const float* w = which ? w2 : w1;
  float v = w[((size_t)l*CCH + c)*CCH + d];
  __half hi = __float2half_rn(v);
  __half lo = __float2half_rn(v - __half2float(hi));
  Whi[t] = hi;
  Wlo[t] = lo;
}

// ======================================================================
// Split-fp16 HMMA GEMM (mma.sync.m16n8k16), fused fp32->fp16 conversion.
// CTA: 128 rows x 128 out-cols, K=128. 8 warps, warp = 16 rows x 128 cols.
// D = Ahi*Whi^T + Alo*Whi^T + Ahi*Wlo^T (fp32 accum).
// ======================================================================
#define PADC 136                        // padded smem row stride in halves
#define OFF_AH 0
#define OFF_AL (128*PADC*2)             // 34816
#define OFF_WH (2*128*PADC*2)           // 69632
#define OFF_WL (OFF_WH + 128*PADC*2)    // 104448
#define OFF_BIAS (OFF_WL + 128*PADC*2)  // 139264
#define GEMM_SMEM (OFF_BIAS + 512)      // 139776

__device__ __forceinline__ void mma16816(float* c, const uint32_t* a, const uint32_t* b){
  asm volatile("mma.sync.aligned.m16n8k16.row.col.f32.f16.f16.f32 "
               "{%0,%1,%2,%3}, {%4,%5,%6,%7}, {%8,%9}, {%0,%1,%2,%3};"
               : "+f"(c[0]), "+f"(c[1]), "+f"(c[2]), "+f"(c[3])
               : "r"(a[0]), "r"(a[1]), "r"(a[2]), "r"(a[3]), "r"(b[0]), "r"(b[1]));
}

__global__ __launch_bounds__(256, 1)
void gemm_kernel(const float* __restrict__ x, const __half* __restrict__ Whi,
                 const __half* __restrict__ Wlo, const float* __restrict__ bias,
                 float* __restrict__ out, __half* __restrict__ out16,
                 int N, int applyPN)
{
  extern __shared__ char smem[];
  const int tid = threadIdx.x;
  const int wid = tid >> 5, lane = tid & 31;
  const int tile = blockIdx.x;
  const int rows = 9*N;
  const int t0 = N >> 7, t1 = t0*4;              // group boundaries in 128-row tiles
  const int l = (tile < t0) ? 0 : ((tile < t1) ? 1 : 2);

  // ---- stage A (fp32 -> split fp16, padded) ----
  #pragma unroll
  for(int i=0;i<16;i++){
    int j = tid + i*256;            // 4096 float4 = 128 rows x 32
    int row = j >> 5, col4 = j & 31;
    int R = tile*128 + row;
    float4 v = make_float4(0.f,0.f,0.f,0.f);
    if(R < rows){
      int n, m; row_to_nm(R, N, n, m);
      v = reinterpret_cast<const float4*>(x)[ ((size_t)n*MTOT + m)*32 + col4 ];
    }
    __half h0 = __float2half_rn(v.x), h1 = __float2half_rn(v.y);
    __half h2 = __float2half_rn(v.z), h3 = __float2half_rn(v.w);
    __half l0 = __float2half_rn(v.x - __half2float(h0));
    __half l1 = __float2half_rn(v.y - __half2float(h1));
    __half l2 = __float2half_rn(v.z - __half2float(h2));
    __half l3 = __float2half_rn(v.w - __half2float(h3));
    uint2 hp, lp;
    hp.x = __half_as_ushort(h0) | ((uint32_t)__half_as_ushort(h1) << 16);
    hp.y = __half_as_ushort(h2) | ((uint32_t)__half_as_ushort(h3) << 16);
    lp.x = __half_as_ushort(l0) | ((uint32_t)__half_as_ushort(l1) << 16);
    lp.y = __half_as_ushort(l2) | ((uint32_t)__half_as_ushort(l3) << 16);
    *reinterpret_cast<uint2*>(smem + OFF_AH + row*(PADC*2) + col4*8) = hp;
    *reinterpret_cast<uint2*>(smem + OFF_AL + row*(PADC*2) + col4*8) = lp;
  }
  // ---- stage W[l] (already split fp16, copy with padding) ----
  {
    const int4* sh = reinterpret_cast<const int4*>(Whi + (size_t)l*CCH*CCH);
    const int4* sl = reinterpret_cast<const int4*>(Wlo + (size_t)l*CCH*CCH);
    #pragma unroll
    for(int i=0;i<8;i++){
      int j = tid + i*256;          // 2048 int4 = 128 rows x 16
      int row = j >> 4, chunk = j & 15;
      *reinterpret_cast<int4*>(smem + OFF_WH + row*(PADC*2) + chunk*16) = sh[j];
      *reinterpret_cast<int4*>(smem + OFF_WL + row*(PADC*2) + chunk*16) = sl[j];
    }
  }
  if(tid < 128) *reinterpret_cast<float*>(smem + OFF_BIAS + tid*4) = bias[tid];
  __syncthreads();

  // ---- mainloop ----
  const int g = lane >> 2, t = lane & 3;
  const int arow0 = wid*16 + g;       // A fragment rows: arow0, arow0+8
  float acc[64];
  #pragma unroll
  for(int i=0;i<64;i++) acc[i] = 0.f;

  #pragma unroll
  for(int ks=0; ks<8; ks++){
    const int k0 = ks*16;
    uint32_t aH[4], aL[4];
    aH[0] = *reinterpret_cast<const uint32_t*>(smem + OFF_AH + (arow0  )*(PADC*2) + (k0 + 2*t    )*2);
    aH[1] = *reinterpret_cast<const uint32_t*>(smem + OFF_AH + (arow0+8)*(PADC*2) + (k0 + 2*t    )*2);
    aH[2] = *reinterpret_cast<const uint32_t*>(smem + OFF_AH + (arow0  )*(PADC*2) + (k0 + 2*t + 8)*2);
    aH[3] = *reinterpret_cast<const uint32_t*>(smem + OFF_AH + (arow0+8)*(PADC*2) + (k0 + 2*t + 8)*2);
    aL[0] = *reinterpret_cast<const uint32_t*>(smem + OFF_AL + (arow0  )*(PADC*2) + (k0 + 2*t    )*2);
    aL[1] = *reinterpret_cast<const uint32_t*>(smem + OFF_AL + (arow0+8)*(PADC*2) + (k0 + 2*t    )*2);
    aL[2] = *reinterpret_cast<const uint32_t*>(smem + OFF_AL + (arow0  )*(PADC*2) + (k0 + 2*t + 8)*2);
    aL[3] = *reinterpret_cast<const uint32_t*>(smem + OFF_AL + (arow0+8)*(PADC*2) + (k0 + 2*t + 8)*2);
    #pragma unroll
    for(int nt=0; nt<16; nt++){
      const int brow = nt*8 + g;      // Wt row = output col index
      uint32_t bH[2], bL[2];
      bH[0] = *reinterpret_cast<const uint32_t*>(smem + OFF_WH + brow*(PADC*2) + (k0 + 2*t    )*2);
      bH[1] = *reinterpret_cast<const uint32_t*>(smem + OFF_WH + brow*(PADC*2) + (k0 + 2*t + 8)*2);
      mma16816(acc + nt*4, aH, bH);
      mma16816(acc + nt*4, aL, bH);
      bL[0] = *reinterpret_cast<const uint32_t*>(smem + OFF_WL + brow*(PADC*2) + (k0 + 2*t    )*2);
      bL[1] = *reinterpret_cast<const uint32_t*>(smem + OFF_WL + brow*(PADC*2) + (k0 + 2*t + 8)*2);
      mma16816(acc + nt*4, aH, bL);
    }
  }

  // ---- epilogue ----
  const float* sbias = reinterpret_cast<const float*>(smem + OFF_BIAS);
  #pragma unroll
  for(int half=0; half<2; half++){
    const int R = tile*128 + arow0 + half*8;
    if(R >= rows) continue;
    int n, m; row_to_nm(R, N, n, m);
    float pn = 1.0f;
    if(applyPN) pn = (m==0) ? 1.0f : ((m<4) ? 0.57735026918962576f : 0.70710678118654752f);
    float* po = out ? (out + ((size_t)n*MTOT + m)*CCH) : nullptr;
    __half2* po16 = out16 ? reinterpret_cast<__half2*>(out16 + ((size_t)n*MTOT + m)*CCH) : nullptr;
    #pragma unroll
    for(int nt=0; nt<16; nt++){
      const int c0 = nt*8 + 2*t;
      float v0 = acc[nt*4 + half*2 + 0];
      float v1 = acc[nt*4 + half*2 + 1];
      if(m == 0){ v0 += sbias[c0]; v1 += sbias[c0+1]; }
      v0 *= pn; v1 *= pn;
      if(po)   *reinterpret_cast<float2*>(po + c0) = make_float2(v0, v1);
      if(po16) po16[c0 >> 1] = __floats2half2_rn(v0, v1);
    }
  }
}

// ======================================================================
// Device: contract accumulated outer-product tensor P with w3j + tpw.
// p1[a*3+b], p2[a*3+b] layout; o[9] output.
// ======================================================================
__device__ __forceinline__ void contract_point(const float* p0, const float* p1, const float* p2,
                                               const float* tpw, const W3J& w, float* o){
  #pragma unroll
  for(int m=0;m<MTOT;m++) o[m]=0.0f;
  // path 0: (0 -> 1)
  #pragma unroll
  for(int c=0;c<3;c++){
    float t=0.f;
    #pragma unroll
    for(int b=0;b<3;b++) t = fmaf(w.v[0 + b*3 + c], p0[b], t);
    o[1+c] = fmaf(tpw[0], t, o[1+c]);
  }
  // path 1: (1 -> 0)
  {
    float t=0.f;
    #pragma unroll
    for(int a=0;a<3;a++)
      #pragma unroll
      for(int b=0;b<3;b++) t = fmaf(w.v[9 + a*3 + b], p1[a*3+b], t);
    o[0] = fmaf(tpw[1], t, o[0]);
  }
  // path 2: (1 -> 1)
  #pragma unroll
  for(int c=0;c<3;c++){
    float t=0.f;
    #pragma unroll
    for(int a=0;a<3;a++)
      #pragma unroll
      for(int b=0;b<3;b++) t = fmaf(w.v[18 + (a*3+b)*3 + c], p1[a*3+b], t);
    o[1+c] = fmaf(tpw[2], t, o[1+c]);
  }
  // path 3: (1 -> 2)
  #pragma unroll
  for(int c=0;c<5;c++){
    float t=0.f;
    #pragma unroll
    for(int a=0;a<3;a++)
      #pragma unroll
      for(int b=0;b<3;b++) t = fmaf(w.v[45 + (a*3+b)*5 + c], p1[a*3+b], t);
    o[4+c] = fmaf(tpw[3], t, o[4+c]);
  }
  // path 4: (2 -> 1)
  #pragma unroll
  for(int c=0;c<3;c++){
    float t=0.f;
    #pragma unroll
    for(int a=0;a<5;a++)
      #pragma unroll
      for(int b=0;b<3;b++) t = fmaf(w.v[90 + (a*3+b)*3 + c], p2[a*3+b], t);
    o[1+c] = fmaf(tpw[4], t, o[1+c]);
  }
  // path 5: (2 -> 2)
  #pragma unroll
  for(int c=0;c<5;c++){
    float t=0.f;
    #pragma unroll
    for(int a=0;a<5;a++)
      #pragma unroll
      for(int b=0;b<3;b++) t = fmaf(w.v[135 + (a*3+b)*5 + c], p2[a*3+b], t);
    o[4+c] = fmaf(tpw[5], t, o[4+c]);
  }
}

// ======================================================================
// Fully fused gather:
//   cdiff[b] = contract(w3j, sum_j a_j * h1[n_j] (x) (y_b - ey_{n_j})) . tpw
// fp16 payload, 2 channels/thread (half2), 64 threads/node, 4 nodes/block.
// ======================================================================
__global__ __launch_bounds__(256)
void gather_kernel(const __half* __restrict__ h1f,
                   const float* __restrict__ pos, const float* __restrict__ exp_pos,
                   const float* __restrict__ alpha, const int* __restrict__ idx,
                   const float* __restrict__ tp_w,
                   float* __restrict__ cdiff, int N1, W3J w, float scale)
{
  const int b = blockIdx.x*4 + (threadIdx.x >> 6);
  if(b >= N1) return;
  const int t = threadIdx.x & 63;
  const int c0 = 2*t;
  const int h = c0 >> 4;

  // P[m][k] = sum_j a_j * h1[n_j][m] * (y_b[k] - ey_{n_j}[k]); float2 = 2 channels
  float2 P[MTOT][3];
  #pragma unroll
  for(int m=0;m<MTOT;m++)
    #pragma unroll
    for(int k=0;k<3;k++) P[m][k] = make_float2(0.f, 0.f);

  float yb[3];
  #pragma unroll
  for(int k=0;k<3;k++) yb[k] = scale * pos[b*3+k];

  const int*   ib = idx   + (size_t)b*KNB;
  const float* ab = alpha + (size_t)b*KNB*HH;

  #pragma unroll 2
  for(int j=0;j<KNB;j++){
    const int n = ib[j];
    const float a = ab[j*HH + h];
    float ady[3];
    #pragma unroll
    for(int k=0;k<3;k++) ady[k] = a * (yb[k] - scale * exp_pos[n*3+k]);
    const __half2* px = reinterpret_cast<const __half2*>(h1f + (size_t)n*MTOT*CCH) + t;
    #pragma unroll
    for(int m=0;m<MTOT;m++){
      float2 v = __half22float2(px[m*64]);
      #pragma unroll
      for(int k=0;k<3;k++){
        P[m][k].x = fmaf(v.x, ady[k], P[m][k].x);
        P[m][k].y = fmaf(v.y, ady[k], P[m][k].y);
      }
    }
  }

  float tpw0[6], tpw1[6];
  #pragma unroll
  for(int p=0;p<6;p++){
    float2 v = *reinterpret_cast<const float2*>(tp_w + p*CCH + c0);
    tpw0[p] = v.x; tpw1[p] = v.y;
  }

  // channel 0
  float p0[3], p1[9], p2[15], o0[MTOT], o1[MTOT];
  #pragma unroll
  for(int k=0;k<3;k++) p0[k] = P[0][k].x;
  #pragma unroll
  for(int a2=0;a2<3;a2++)
    #pragma unroll
    for(int k=0;k<3;k++) p1[a2*3+k] = P[1+a2][k].x;
  #pragma unroll
  for(int a2=0;a2<5;a2++)
    #pragma unroll
    for(int k=0;k<3;k++) p2[a2*3+k] = P[4+a2][k].x;
  contract_point(p0, p1, p2, tpw0, w, o0);
  // channel 1
  #pragma unroll
  for(int k=0;k<3;k++) p0[k] = P[0][k].y;
  #pragma unroll
  for(int a2=0;a2<3;a2++)
    #pragma unroll
    for(int k=0;k<3;k++) p1[a2*3+k] = P[1+a2][k].y;
  #pragma unroll
  for(int a2=0;a2<5;a2++)
    #pragma unroll
    for(int k=0;k<3;k++) p2[a2*3+k] = P[4+a2][k].y;
  contract_point(p0, p1, p2, tpw1, w, o1);

  float* od = cdiff + (size_t)b*MTOT*CCH + c0;
  #pragma unroll
  for(int m=0;m<MTOT;m++)
    *reinterpret_cast<float2*>(od + m*CCH) = make_float2(o0[m], o1[m]);
}

// ======================================================================
// launch
// ======================================================================
extern "C" void kernel_launch(void* const* d_in, const int* in_sizes, int n_in,
                              void* d_out, int out_size)
{
  const float* pos     = (const float*)d_in[0];
  const float* exp_pos = (const float*)d_in[1];
  // d_in[2] = h : unused by the reference
  const float* exp_h   = (const float*)d_in[3];
  const float* alpha   = (const float*)d_in[4];
  const int*   idx     = (const int*)  d_in[5];
  const float* w1w     = (const float*)d_in[6];
  const float* w1b     = (const float*)d_in[7];
  const float* w2w     = (const float*)d_in[8];
  const float* w2b     = (const float*)d_in[9];
  const float* tpw     = (const float*)d_in[10];

  const int N1 = in_sizes[0]/3;
  const int N2 = in_sizes[1]/3;

  W3J w;
  build_w3j(&w);
  const double PI = 3.14159265358979323846;
  const float scale = (float)(2.04665350914 * std::sqrt(3.0/(4.0*PI)));  // COEF1 * SH1_INT

  float *p_cd=nullptr;
  __half *p_h1f=nullptr, *p_whi=nullptr, *p_wlo=nullptr;
  cudaGetSymbolAddress((void**)&p_cd,  g_cdiff);
  cudaGetSymbolAddress((void**)&p_h1f, g_h1f16);
  cudaGetSymbolAddress((void**)&p_whi, g_Whi);
  cudaGetSymbolAddress((void**)&p_wlo, g_Wlo);

  cudaFuncSetAttribute(gemm_kernel, cudaFuncAttributeMaxDynamicSharedMemorySize, GEMM_SMEM);

  const int tiles2 = (9*N2 + 127) >> 7;   // 288 for N2=4096
  const int tiles1 = (9*N1 + 127) >> 7;

  // 0) W images (both linears, hi/lo, transposed)
  conv_w_kernel<<<(2*3*CCH*CCH + 255)/256, 256>>>(w1w, w2w, p_whi, p_wlo);
  // 1) h1f16 = fp16( so3_linear(exp_h, w1) )   [fp16-only output]
  gemm_kernel<<<tiles2, 256, GEMM_SMEM>>>(exp_h, p_whi, p_wlo, w1b, nullptr, p_h1f, N2, 0);
  // 2) fused gather + both tensor products via bilinearity
  gather_kernel<<<(N1+3)/4, 256>>>(p_h1f, pos, exp_pos, alpha, idx, tpw, p_cd, N1, w, scale);
  // 3) out = so3_linear(cdiff, w2) * PATH_NORM
  gemm_kernel<<<tiles1, 256, GEMM_SMEM>>>(p_cd, p_whi + 3*CCH*CCH, p_wlo + 3*CCH*CCH,
                                          w2b, (float*)d_out, nullptr, N1, 1);
}

// round 7
// speedup vs baseline: 2.3371x; 1.0114x over previous
#include <cuda_runtime.h>
#include <cuda_fp16.h>
#include <cmath>
#include <complex>
#include <algorithm>
#include <cstdint>

// ---------------- problem constants ----------------
#define MTOT 9        // (LMAX+1)^2
#define CCH  128      // channels
#define KNB  16       // neighbors
#define HH   8        // heads
#define MAXN 4096     // max nodes (matches setup)

struct W3J { float v[210]; };   // packed per-path: (0,1)@0:9 (1,0)@9:9 (1,1)@18:27 (1,2)@45:45 (2,1)@90:45 (2,2)@135:75

// ---------------- scratch (static device globals; no allocation) ----------------
__device__ float  g_cdiff [MAXN * MTOT * CCH];
__device__ __half g_h1f16 [MAXN * MTOT * CCH];     // fp16 gather payload
__device__ __half g_Whi[2 * 3 * CCH * CCH];        // transposed: [which][l][d_out][c_in]
__device__ __half g_Wlo[2 * 3 * CCH * CCH];

// ======================================================================
// Host-side real Wigner-3j construction (port of the e3nn-style reference)
// ======================================================================
static double hfact(int n){ double r=1.0; for(int i=2;i<=n;i++) r*= (double)i; return r; }

static double su2_cg(int j1,int j2,int j3,int m1,int m2,int m3){
  if(m3 != m1+m2) return 0.0;
  if(j3 < std::abs(j1-j2) || j3 > j1+j2) return 0.0;
  double pref = std::sqrt((2.0*j3+1.0)*hfact(j1+j2-j3)*hfact(j1-j2+j3)*hfact(-j1+j2+j3)/hfact(j1+j2+j3+1));
  pref *= std::sqrt(hfact(j3+m3)*hfact(j3-m3)*hfact(j1-m1)*hfact(j1+m1)*hfact(j2-m2)*hfact(j2+m2));
  int vmin = std::max(0, std::max(j2-j3-m1, j1-j3+m2));
  int vmax = std::min(j1+j2-j3, std::min(j1-m1, j2+m2));
  double s=0.0;
  for(int v=vmin; v<=vmax; v++){
    double den = hfact(v)*hfact(j1+j2-j3-v)*hfact(j1-m1-v)*hfact(j2+m2-v)*hfact(j3-j2+m1+v)*hfact(j3-j1-m2+v);
    s += ((v&1)? -1.0 : 1.0)/den;
  }
  return pref*s;
}

static void q_r2c(int l, std::complex<double>* q){
  int n = 2*l+1;
  for(int i=0;i<n*n;i++) q[i]=std::complex<double>(0.0,0.0);
  double is2 = 1.0/std::sqrt(2.0);
  for(int m=-l;m<0;m++){
    q[(l+m)*n + (l-m)] = std::complex<double>(is2, 0.0);
    q[(l+m)*n + (l+m)] = std::complex<double>(0.0,-is2);
  }
  q[l*n + l] = std::complex<double>(1.0,0.0);
  for(int m=1;m<=l;m++){
    double sg = (m&1)? -1.0 : 1.0;
    q[(l+m)*n + (l+m)] = std::complex<double>(sg*is2, 0.0);
    q[(l+m)*n + (l-m)] = std::complex<double>(0.0, sg*is2);
  }
  std::complex<double> f(1.0,0.0), mi(0.0,-1.0);
  for(int i=0;i<l;i++) f *= mi;
  for(int i=0;i<n*n;i++) q[i] *= f;
}

static void real_w3j(int l1, int l3, float* out){
  const int n1=2*l1+1, n2=3, n3=2*l3+1;
  std::complex<double> Cc[5*3*5];
  for(int i=0;i<n1;i++) for(int j=0;j<n2;j++) for(int k=0;k<n3;k++)
    Cc[(i*n2+j)*n3+k] = std::complex<double>(su2_cg(l1,1,l3, i-l1, j-1, k-l3), 0.0);
  std::complex<double> Q1[25],Q2[9],Q3[25];
  q_r2c(l1,Q1); q_r2c(1,Q2); q_r2c(l3,Q3);
  std::complex<double> C[5*3*5];
  for(int a=0;a<n1;a++) for(int b=0;b<n2;b++) for(int c=0;c<n3;c++){
    std::complex<double> s(0.0,0.0);
    for(int i=0;i<n1;i++) for(int j=0;j<n2;j++) for(int k=0;k<n3;k++)
      s += Q1[i*n1+a]*Q2[j*n2+b]*std::conj(Q3[k*n3+c])*Cc[(i*n2+j)*n3+k];
    C[(a*n2+b)*n3+c]=s;
  }
  double sr=0.0, si=0.0;
  for(int i=0;i<n1*n2*n3;i++){ sr += std::fabs(C[i].real()); si += std::fabs(C[i].imag()); }
  double vals[75]; double norm=0.0;
  for(int i=0;i<n1*n2*n3;i++){ double v=(sr>=si)? C[i].real() : C[i].imag(); vals[i]=v; norm+=v*v; }
  norm = std::sqrt(norm);
  double sc = std::sqrt((double)(2*l3+1))/norm;
  for(int i=0;i<n1*n2*n3;i++) out[i] = (float)(vals[i]*sc);
}

static void build_w3j(W3J* w){
  real_w3j(0,1, w->v+0);
  real_w3j(1,0, w->v+9);
  real_w3j(1,1, w->v+18);
  real_w3j(1,2, w->v+45);
  real_w3j(2,1, w->v+90);
  real_w3j(2,2, w->v+135);
}

// ======================================================================
// Row mapping: GEMM rows grouped by degree.
// ======================================================================
__device__ __forceinline__ void row_to_nm(int R, int N, int& n, int& m){
  if(R < N){ n = R; m = 0; }
  else if(R < 4*N){ int q = R - N; n = q/3; m = 1 + q%3; }
  else { int q = R - 4*N; n = q/5; m = 4 + q%5; }
}

__device__ __forceinline__ uint32_t smem_u32(const void* p){
  uint32_t a;
  asm("{ .reg .u64 t; cvta.to.shared.u64 t, %1; cvt.u32.u64 %0, t; }" : "=r"(a) : "l"(p));
  return a;
}

// ======================================================================
// W conversion: W[l][c][d] fp32 -> transposed split-fp16 Wt[which][l][d][c]
// ======================================================================
__global__ __launch_bounds__(256)
void conv_w_kernel(const float* __restrict__ w1, const float* __restrict__ w2,
                   __half* __restrict__ Whi, __half* __restrict__ Wlo)
{
  int t = blockIdx.x*256 + threadIdx.x;
  if(t >= 2*3*CCH*CCH) return;
  int which = t / (3*CCH*CCH);
  int rem = t % (3*CCH*CCH);
  int l = rem / (CCH*CCH);
  int e = rem % (CCH*CCH);
  int d = e >> 7, c = e & 127;
  const float* w = which ? w2 : w1;
  float v = w[((size_t)l*CCH + c)*CCH + d];
  __half hi = __float2half_rn(v);
  __half lo = __float2half_rn(v - __half2float(hi));
  Whi[t] = hi;
  Wlo[t] = lo;
}

// ======================================================================
// Split-fp16 HMMA GEMM (mma.sync.m16n8k16 + ldmatrix), fused conversion.
// CTA: 128 rows x 64 out-cols (2D grid: row-tile x col-half), K=128.
// 8 warps; warp = 16 rows x 64 cols. 2 CTAs/SM (104.7KB smem).
// D = Ahi*Whi^T + Alo*Whi^T + Ahi*Wlo^T (fp32 accum).
// ======================================================================
#define PADC 136                        // padded smem row stride in halves (272B)
#define OFF_AH 0
#define OFF_AL (128*PADC*2)             // 34816
#define OFF_WH (2*128*PADC*2)           // 69632
#define OFF_WL (OFF_WH + 64*PADC*2)     // 87040
#define OFF_BIAS (OFF_WL + 64*PADC*2)   // 104448
#define GEMM_SMEM (OFF_BIAS + 256)      // 104704

__device__ __forceinline__ void mma16816(float* c, const uint32_t* a, const uint32_t* b){
  asm volatile("mma.sync.aligned.m16n8k16.row.col.f32.f16.f16.f32 "
               "{%0,%1,%2,%3}, {%4,%5,%6,%7}, {%8,%9}, {%0,%1,%2,%3};"
               : "+f"(c[0]), "+f"(c[1]), "+f"(c[2]), "+f"(c[3])
               : "r"(a[0]), "r"(a[1]), "r"(a[2]), "r"(a[3]), "r"(b[0]), "r"(b[1]));
}

#define LDSM4(r, addr) \
  asm volatile("ldmatrix.sync.aligned.m8n8.x4.shared.b16 {%0,%1,%2,%3}, [%4];" \
               : "=r"((r)[0]), "=r"((r)[1]), "=r"((r)[2]), "=r"((r)[3]) : "r"(addr))

#define CP_ASYNC16(dst, src) \
  asm volatile("cp.async.ca.shared.global [%0], [%1], 16;" :: "r"(dst), "l"(src))

__global__ __launch_bounds__(256, 2)
void gemm_kernel(const float* __restrict__ x, const __half* __restrict__ Whi,
                 const __half* __restrict__ Wlo, const float* __restrict__ bias,
                 float* __restrict__ out, __half* __restrict__ out16,
                 int N, int applyPN)
{
  extern __shared__ char smem[];
  const uint32_t sb = smem_u32(smem);
  const int tid = threadIdx.x;
  const int wid = tid >> 5, lane = tid & 31;
  const int tile = blockIdx.x;
  const int colhalf = blockIdx.y;          // 0 or 1: output cols [colhalf*64, +64)
  const int rows = 9*N;
  const int t0 = N >> 7, t1 = t0*4;        // group boundaries in 128-row tiles
  const int l = (tile < t0) ? 0 : ((tile < t1) ? 1 : 2);

  // ---- async stage W[l] rows [colhalf*64, +64) (hi+lo, padded) ----
  {
    const char* srcH = (const char*)(Whi + (size_t)l*CCH*CCH + (size_t)colhalf*64*CCH);
    const char* srcL = (const char*)(Wlo + (size_t)l*CCH*CCH + (size_t)colhalf*64*CCH);
    #pragma unroll
    for(int i=0;i<4;i++){
      int j = tid + i*256;                 // 1024 16B-chunks = 64 rows x 16
      int row = j >> 4, chunk = j & 15;
      CP_ASYNC16(sb + OFF_WH + row*(PADC*2) + chunk*16, srcH + row*256 + chunk*16);
      CP_ASYNC16(sb + OFF_WL + row*(PADC*2) + chunk*16, srcL + row*256 + chunk*16);
    }
    asm volatile("cp.async.commit_group;");
  }
  if(tid < 64) *reinterpret_cast<float*>(smem + OFF_BIAS + tid*4) = bias[colhalf*64 + tid];

  // ---- stage A (fp32 -> split fp16, padded) ----
  #pragma unroll
  for(int i=0;i<16;i++){
    int j = tid + i*256;            // 4096 float4 = 128 rows x 32
    int row = j >> 5, col4 = j & 31;
    int R = tile*128 + row;
    float4 v = make_float4(0.f,0.f,0.f,0.f);
    if(R < rows){
      int n, m; row_to_nm(R, N, n, m);
      v = reinterpret_cast<const float4*>(x)[ ((size_t)n*MTOT + m)*32 + col4 ];
    }
    __half h0 = __float2half_rn(v.x), h1 = __float2half_rn(v.y);
    __half h2 = __float2half_rn(v.z), h3 = __float2half_rn(v.w);
    __half l0 = __float2half_rn(v.x - __half2float(h0));
    __half l1 = __float2half_rn(v.y - __half2float(h1));
    __half l2 = __float2half_rn(v.z - __half2float(h2));
    __half l3 = __float2half_rn(v.w - __half2float(h3));
    uint2 hp, lp;
    hp.x = __half_as_ushort(h0) | ((uint32_t)__half_as_ushort(h1) << 16);
    hp.y = __half_as_ushort(h2) | ((uint32_t)__half_as_ushort(h3) << 16);
    lp.x = __half_as_ushort(l0) | ((uint32_t)__half_as_ushort(l1) << 16);
    lp.y = __half_as_ushort(l2) | ((uint32_t)__half_as_ushort(l3) << 16);
    *reinterpret_cast<uint2*>(smem + OFF_AH + row*(PADC*2) + col4*8) = hp;
    *reinterpret_cast<uint2*>(smem + OFF_AL + row*(PADC*2) + col4*8) = lp;
  }
  asm volatile("cp.async.wait_group 0;");
  __syncthreads();

  // ---- ldmatrix per-lane base addresses ----
  const int g = lane >> 2, t = lane & 3;
  const int lr = lane & 7, aw = lane >> 3;             // tile index 0..3
  // A x4: tile0 rows+0/k0, tile1 rows+8/k0, tile2 rows+0/k0+8, tile3 rows+8/k0+8
  const int arow_lane = wid*16 + lr + (aw & 1)*8;
  const int acol_lane = (aw >> 1)*8;
  const uint32_t aH_base = sb + OFF_AH + arow_lane*(PADC*2) + acol_lane*2;
  const uint32_t aL_base = sb + OFF_AL + arow_lane*(PADC*2) + acol_lane*2;
  // B x4 (2 n-tiles): tile0 n0 rows/k0, tile1 n0/k0+8, tile2 n1/k0, tile3 n1/k0+8
  const int brow_rel = ((lane >> 4) << 3) + lr;
  const int bcol_lane = ((lane >> 3) & 1)*8;
  const uint32_t bH_base = sb + OFF_WH + brow_rel*(PADC*2) + bcol_lane*2;
  const uint32_t bL_base = sb + OFF_WL + brow_rel*(PADC*2) + bcol_lane*2;

  float acc[32];
  #pragma unroll
  for(int i=0;i<32;i++) acc[i] = 0.f;

  #pragma unroll
  for(int ks=0; ks<8; ks++){
    const uint32_t ko = ks*32;           // k0*2 bytes
    uint32_t aH[4], aL[4];
    LDSM4(aH, aH_base + ko);
    LDSM4(aL, aL_base + ko);
    #pragma unroll
    for(int ntp=0; ntp<4; ntp++){
      uint32_t bH[4], bL[4];
      LDSM4(bH, bH_base + ntp*16*(PADC*2) + ko);
      LDSM4(bL, bL_base + ntp*16*(PADC*2) + ko);
      mma16816(acc + (2*ntp  )*4, aH, bH);
      mma16816(acc + (2*ntp  )*4, aL, bH);
      mma16816(acc + (2*ntp  )*4, aH, bL);
      mma16816(acc + (2*ntp+1)*4, aH, bH+2);
      mma16816(acc + (2*ntp+1)*4, aL, bH+2);
      mma16816(acc + (2*ntp+1)*4, aH, bL+2);
    }
  }

  // ---- epilogue ----
  const float* sbias = reinterpret_cast<const float*>(smem + OFF_BIAS);
  #pragma unroll
  for(int half=0; half<2; half++){
    const int R = tile*128 + wid*16 + g + half*8;
    if(R >= rows) continue;
    int n, m; row_to_nm(R, N, n, m);
    float pn = 1.0f;
    if(applyPN) pn = (m==0) ? 1.0f : ((m<4) ? 0.57735026918962576f : 0.70710678118654752f);
    float* po = out ? (out + ((size_t)n*MTOT + m)*CCH + colhalf*64) : nullptr;
    __half2* po16 = out16 ? reinterpret_cast<__half2*>(out16 + ((size_t)n*MTOT + m)*CCH + colhalf*64) : nullptr;
    #pragma unroll
    for(int nt=0; nt<8; nt++){
      const int c0 = nt*8 + 2*t;
      float v0 = acc[nt*4 + half*2 + 0];
      float v1 = acc[nt*4 + half*2 + 1];
      if(m == 0){ v0 += sbias[c0]; v1 += sbias[c0+1]; }
      v0 *= pn; v1 *= pn;
      if(po)   *reinterpret_cast<float2*>(po + c0) = make_float2(v0, v1);
      if(po16) po16[c0 >> 1] = __floats2half2_rn(v0, v1);
    }
  }
}

// ======================================================================
// Device: contract accumulated outer-product tensor P with w3j + tpw.
// ======================================================================
__device__ __forceinline__ void contract_point(const float* p0, const float* p1, const float* p2,
                                               const float* tpw, const W3J& w, float* o){
  #pragma unroll
  for(int m=0;m<MTOT;m++) o[m]=0.0f;
  #pragma unroll
  for(int c=0;c<3;c++){
    float t=0.f;
    #pragma unroll
    for(int b=0;b<3;b++) t = fmaf(w.v[0 + b*3 + c], p0[b], t);
    o[1+c] = fmaf(tpw[0], t, o[1+c]);
  }
  {
    float t=0.f;
    #pragma unroll
    for(int a=0;a<3;a++)
      #pragma unroll
      for(int b=0;b<3;b++) t = fmaf(w.v[9 + a*3 + b], p1[a*3+b], t);
    o[0] = fmaf(tpw[1], t, o[0]);
  }
  #pragma unroll
  for(int c=0;c<3;c++){
    float t=0.f;
    #pragma unroll
    for(int a=0;a<3;a++)
      #pragma unroll
      for(int b=0;b<3;b++) t = fmaf(w.v[18 + (a*3+b)*3 + c], p1[a*3+b], t);
    o[1+c] = fmaf(tpw[2], t, o[1+c]);
  }
  #pragma unroll
  for(int c=0;c<5;c++){
    float t=0.f;
    #pragma unroll
    for(int a=0;a<3;a++)
      #pragma unroll
      for(int b=0;b<3;b++) t = fmaf(w.v[45 + (a*3+b)*5 + c], p1[a*3+b], t);
    o[4+c] = fmaf(tpw[3], t, o[4+c]);
  }
  #pragma unroll
  for(int c=0;c<3;c++){
    float t=0.f;
    #pragma unroll
    for(int a=0;a<5;a++)
      #pragma unroll
      for(int b=0;b<3;b++) t = fmaf(w.v[90 + (a*3+b)*3 + c], p2[a*3+b], t);
    o[1+c] = fmaf(tpw[4], t, o[1+c]);
  }
  #pragma unroll
  for(int c=0;c<5;c++){
    float t=0.f;
    #pragma unroll
    for(int a=0;a<5;a++)
      #pragma unroll
      for(int b=0;b<3;b++) t = fmaf(w.v[135 + (a*3+b)*5 + c], p2[a*3+b], t);
    o[4+c] = fmaf(tpw[5], t, o[4+c]);
  }
}

// ======================================================================
// Fully fused gather:
//   cdiff[b] = contract(w3j, sum_j a_j * h1[n_j] (x) (y_b - ey_{n_j})) . tpw
// ======================================================================
__global__ __launch_bounds__(256)
void gather_kernel(const __half* __restrict__ h1f,
                   const float* __restrict__ pos, const float* __restrict__ exp_pos,
                   const float* __restrict__ alpha, const int* __restrict__ idx,
                   const float* __restrict__ tp_w,
                   float* __restrict__ cdiff, int N1, W3J w, float scale)
{
  const int b = blockIdx.x*4 + (threadIdx.x >> 6);
  if(b >= N1) return;
  const int t = threadIdx.x & 63;
  const int c0 = 2*t;
  const int h = c0 >> 4;

  float2 P[MTOT][3];
  #pragma unroll
  for(int m=0;m<MTOT;m++)
    #pragma unroll
    for(int k=0;k<3;k++) P[m][k] = make_float2(0.f, 0.f);

  float yb[3];
  #pragma unroll
  for(int k=0;k<3;k++) yb[k] = scale * pos[b*3+k];

  const int*   ib = idx   + (size_t)b*KNB;
  const float* ab = alpha + (size_t)b*KNB*HH;

  #pragma unroll 2
  for(int j=0;j<KNB;j++){
    const int n = ib[j];
    const float a = ab[j*HH + h];
    float ady[3];
    #pragma unroll
    for(int k=0;k<3;k++) ady[k] = a * (yb[k] - scale * exp_pos[n*3+k]);
    const __half2* px = reinterpret_cast<const __half2*>(h1f + (size_t)n*MTOT*CCH) + t;
    #pragma unroll
    for(int m=0;m<MTOT;m++){
      float2 v = __half22float2(px[m*64]);
      #pragma unroll
      for(int k=0;k<3;k++){
        P[m][k].x = fmaf(v.x, ady[k], P[m][k].x);
        P[m][k].y = fmaf(v.y, ady[k], P[m][k].y);
      }
    }
  }

  float tpw0[6], tpw1[6];
  #pragma unroll
  for(int p=0;p<6;p++){
    float2 v = *reinterpret_cast<const float2*>(tp_w + p*CCH + c0);
    tpw0[p] = v.x; tpw1[p] = v.y;
  }

  float p0[3], p1[9], p2[15], o0[MTOT], o1[MTOT];
  #pragma unroll
  for(int k=0;k<3;k++) p0[k] = P[0][k].x;
  #pragma unroll
  for(int a2=0;a2<3;a2++)
    #pragma unroll
    for(int k=0;k<3;k++) p1[a2*3+k] = P[1+a2][k].x;
  #pragma unroll
  for(int a2=0;a2<5;a2++)
    #pragma unroll
    for(int k=0;k<3;k++) p2[a2*3+k] = P[4+a2][k].x;
  contract_point(p0, p1, p2, tpw0, w, o0);
  #pragma unroll
  for(int k=0;k<3;k++) p0[k] = P[0][k].y;
  #pragma unroll
  for(int a2=0;a2<3;a2++)
    #pragma unroll
    for(int k=0;k<3;k++) p1[a2*3+k] = P[1+a2][k].y;
  #pragma unroll
  for(int a2=0;a2<5;a2++)
    #pragma unroll
    for(int k=0;k<3;k++) p2[a2*3+k] = P[4+a2][k].y;
  contract_point(p0, p1, p2, tpw1, w, o1);

  float* od = cdiff + (size_t)b*MTOT*CCH + c0;
  #pragma unroll
  for(int m=0;m<MTOT;m++)
    *reinterpret_cast<float2*>(od + m*CCH) = make_float2(o0[m], o1[m]);
}

// ======================================================================
// launch
// ======================================================================
extern "C" void kernel_launch(void* const* d_in, const int* in_sizes, int n_in,
                              void* d_out, int out_size)
{
  const float* pos     = (const float*)d_in[0];
  const float* exp_pos = (const float*)d_in[1];
  // d_in[2] = h : unused by the reference
  const float* exp_h   = (const float*)d_in[3];
  const float* alpha   = (const float*)d_in[4];
  const int*   idx     = (const int*)  d_in[5];
  const float* w1w     = (const float*)d_in[6];
  const float* w1b     = (const float*)d_in[7];
  const float* w2w     = (const float*)d_in[8];
  const float* w2b     = (const float*)d_in[9];
  const float* tpw     = (const float*)d_in[10];

  const int N1 = in_sizes[0]/3;
  const int N2 = in_sizes[1]/3;

  W3J w;
  build_w3j(&w);
  const double PI = 3.14159265358979323846;
  const float scale = (float)(2.04665350914 * std::sqrt(3.0/(4.0*PI)));  // COEF1 * SH1_INT

  float *p_cd=nullptr;
  __half *p_h1f=nullptr, *p_whi=nullptr, *p_wlo=nullptr;
  cudaGetSymbolAddress((void**)&p_cd,  g_cdiff);
  cudaGetSymbolAddress((void**)&p_h1f, g_h1f16);
  cudaGetSymbolAddress((void**)&p_whi, g_Whi);
  cudaGetSymbolAddress((void**)&p_wlo, g_Wlo);

  cudaFuncSetAttribute(gemm_kernel, cudaFuncAttributeMaxDynamicSharedMemorySize, GEMM_SMEM);

  const int tiles2 = (9*N2 + 127) >> 7;   // 288 for N2=4096
  const int tiles1 = (9*N1 + 127) >> 7;

  // 0) W images (both linears, hi/lo, transposed)
  conv_w_kernel<<<(2*3*CCH*CCH + 255)/256, 256>>>(w1w, w2w, p_whi, p_wlo);
  // 1) h1f16 = fp16( so3_linear(exp_h, w1) )   [fp16-only output]
  gemm_kernel<<<dim3(tiles2, 2), 256, GEMM_SMEM>>>(exp_h, p_whi, p_wlo, w1b, nullptr, p_h1f, N2, 0);
  // 2) fused gather + both tensor products via bilinearity
  gather_kernel<<<(N1+3)/4, 256>>>(p_h1f, pos, exp_pos, alpha, idx, tpw, p_cd, N1, w, scale);
  // 3) out = so3_linear(cdiff, w2) * PATH_NORM
  gemm_kernel<<<dim3(tiles1, 2), 256, GEMM_SMEM>>>(p_cd, p_whi + 3*CCH*CCH, p_wlo + 3*CCH*CCH,
                                                   w2b, (float*)d_out, nullptr, N1, 1);
}

// round 8
// speedup vs baseline: 3.4082x; 1.4583x over previous
#include <cuda_runtime.h>
#include <cuda_fp16.h>
#include <cmath>
#include <complex>
#include <algorithm>
#include <cstdint>

// ---------------- problem constants ----------------
#define MTOT 9        // (LMAX+1)^2
#define CCH  128      // channels
#define KNB  16       // neighbors
#define HH   8        // heads
#define MAXN 4096     // max nodes (matches setup)

struct W3J { float v[210]; };

// ---------------- scratch (static device globals; no allocation) ----------------
__device__ float  g_cdiff [MAXN * MTOT * CCH];
__device__ __half g_h1f16 [MAXN * MTOT * CCH];     // fp16 gather payload
__device__ __half g_Whi[2 * 3 * CCH * CCH];        // transposed: [which][l][d_out][c_in]

// ======================================================================
// Host-side real Wigner-3j construction (port of the e3nn-style reference)
// ======================================================================
static double hfact(int n){ double r=1.0; for(int i=2;i<=n;i++) r*= (double)i; return r; }

static double su2_cg(int j1,int j2,int j3,int m1,int m2,int m3){
  if(m3 != m1+m2) return 0.0;
  if(j3 < std::abs(j1-j2) || j3 > j1+j2) return 0.0;
  double pref = std::sqrt((2.0*j3+1.0)*hfact(j1+j2-j3)*hfact(j1-j2+j3)*hfact(-j1+j2+j3)/hfact(j1+j2+j3+1));
  pref *= std::sqrt(hfact(j3+m3)*hfact(j3-m3)*hfact(j1-m1)*hfact(j1+m1)*hfact(j2-m2)*hfact(j2+m2));
  int vmin = std::max(0, std::max(j2-j3-m1, j1-j3+m2));
  int vmax = std::min(j1+j2-j3, std::min(j1-m1, j2+m2));
  double s=0.0;
  for(int v=vmin; v<=vmax; v++){
    double den = hfact(v)*hfact(j1+j2-j3-v)*hfact(j1-m1-v)*hfact(j2+m2-v)*hfact(j3-j2+m1+v)*hfact(j3-j1-m2+v);
    s += ((v&1)? -1.0 : 1.0)/den;
  }
  return pref*s;
}

static void q_r2c(int l, std::complex<double>* q){
  int n = 2*l+1;
  for(int i=0;i<n*n;i++) q[i]=std::complex<double>(0.0,0.0);
  double is2 = 1.0/std::sqrt(2.0);
  for(int m=-l;m<0;m++){
    q[(l+m)*n + (l-m)] = std::complex<double>(is2, 0.0);
    q[(l+m)*n + (l+m)] = std::complex<double>(0.0,-is2);
  }
  q[l*n + l] = std::complex<double>(1.0,0.0);
  for(int m=1;m<=l;m++){
    double sg = (m&1)? -1.0 : 1.0;
    q[(l+m)*n + (l+m)] = std::complex<double>(sg*is2, 0.0);
    q[(l+m)*n + (l-m)] = std::complex<double>(0.0, sg*is2);
  }
  std::complex<double> f(1.0,0.0), mi(0.0,-1.0);
  for(int i=0;i<l;i++) f *= mi;
  for(int i=0;i<n*n;i++) q[i] *= f;
}

static void real_w3j(int l1, int l3, float* out){
  const int n1=2*l1+1, n2=3, n3=2*l3+1;
  std::complex<double> Cc[5*3*5];
  for(int i=0;i<n1;i++) for(int j=0;j<n2;j++) for(int k=0;k<n3;k++)
    Cc[(i*n2+j)*n3+k] = std::complex<double>(su2_cg(l1,1,l3, i-l1, j-1, k-l3), 0.0);
  std::complex<double> Q1[25],Q2[9],Q3[25];
  q_r2c(l1,Q1); q_r2c(1,Q2); q_r2c(l3,Q3);
  std::complex<double> C[5*3*5];
  for(int a=0;a<n1;a++) for(int b=0;b<n2;b++) for(int c=0;c<n3;c++){
    std::complex<double> s(0.0,0.0);
    for(int i=0;i<n1;i++) for(int j=0;j<n2;j++) for(int k=0;k<n3;k++)
      s += Q1[i*n1+a]*Q2[j*n2+b]*std::conj(Q3[k*n3+c])*Cc[(i*n2+j)*n3+k];
    C[(a*n2+b)*n3+c]=s;
  }
  double sr=0.0, si=0.0;
  for(int i=0;i<n1*n2*n3;i++){ sr += std::fabs(C[i].real()); si += std::fabs(C[i].imag()); }
  double vals[75]; double norm=0.0;
  for(int i=0;i<n1*n2*n3;i++){ double v=(sr>=si)? C[i].real() : C[i].imag(); vals[i]=v; norm+=v*v; }
  norm = std::sqrt(norm);
  double sc = std::sqrt((double)(2*l3+1))/norm;
  for(int i=0;i<n1*n2*n3;i++) out[i] = (float)(vals[i]*sc);
}

static void build_w3j(W3J* w){
  real_w3j(0,1, w->v+0);
  real_w3j(1,0, w->v+9);
  real_w3j(1,1, w->v+18);
  real_w3j(1,2, w->v+45);
  real_w3j(2,1, w->v+90);
  real_w3j(2,2, w->v+135);
}

// ======================================================================
// Row mapping: GEMM rows grouped by degree.
// ======================================================================
__device__ __forceinline__ void row_to_nm(int R, int N, int& n, int& m){
  if(R < N){ n = R; m = 0; }
  else if(R < 4*N){ int q = R - N; n = q/3; m = 1 + q%3; }
  else { int q = R - 4*N; n = q/5; m = 4 + q%5; }
}

__device__ __forceinline__ uint32_t smem_u32(const void* p){
  uint32_t a;
  asm("{ .reg .u64 t; cvta.to.shared.u64 t, %1; cvt.u32.u64 %0, t; }" : "=r"(a) : "l"(p));
  return a;
}

// ======================================================================
// W conversion: W[l][c][d] fp32 -> transposed fp16 Wt[which][l][d][c]
// ======================================================================
__global__ __launch_bounds__(256)
void conv_w_kernel(const float* __restrict__ w1, const float* __restrict__ w2,
                   __half* __restrict__ Whi)
{
  int t = blockIdx.x*256 + threadIdx.x;
  if(t >= 2*3*CCH*CCH) return;
  int which = t / (3*CCH*CCH);
  int rem = t % (3*CCH*CCH);
  int l = rem / (CCH*CCH);
  int e = rem % (CCH*CCH);
  int d = e >> 7, c = e & 127;
  const float* w = which ? w2 : w1;
  Whi[t] = __float2half_rn(w[((size_t)l*CCH + c)*CCH + d]);
}

// ======================================================================
// HMMA GEMM common pieces
// ======================================================================
#define PADC 136                        // padded smem row stride in halves (272B)

__device__ __forceinline__ void mma16816(float* c, const uint32_t* a, const uint32_t* b){
  asm volatile("mma.sync.aligned.m16n8k16.row.col.f32.f16.f16.f32 "
               "{%0,%1,%2,%3}, {%4,%5,%6,%7}, {%8,%9}, {%0,%1,%2,%3};"
               : "+f"(c[0]), "+f"(c[1]), "+f"(c[2]), "+f"(c[3])
               : "r"(a[0]), "r"(a[1]), "r"(a[2]), "r"(a[3]), "r"(b[0]), "r"(b[1]));
}

#define LDSM4(r, addr) \
  asm volatile("ldmatrix.sync.aligned.m8n8.x4.shared.b16 {%0,%1,%2,%3}, [%4];" \
               : "=r"((r)[0]), "=r"((r)[1]), "=r"((r)[2]), "=r"((r)[3]) : "r"(addr))

#define CP_ASYNC16(dst, src) \
  asm volatile("cp.async.ca.shared.global [%0], [%1], 16;" :: "r"(dst), "l"(src))

// ======================================================================
// GEMM1: single-term fp16 (A_hi * W_hi), output fp16 only.
// CTA: 128x128 tile, K=128, 512 threads (16 warps: warp=(16 rows)x(64 cols)).
// smem: A 34816 + W 34816 + bias 512 = 70144 -> 2 CTAs/SM.
// ======================================================================
#define G1_OFF_A 0
#define G1_OFF_W (128*PADC*2)            // 34816
#define G1_OFF_BIAS (2*128*PADC*2)       // 69632
#define G1_SMEM (G1_OFF_BIAS + 512)      // 70144

__global__ __launch_bounds__(512, 2)
void gemm1_kernel(const float* __restrict__ x, const __half* __restrict__ Whi,
                  const float* __restrict__ bias, __half* __restrict__ out16, int N)
{
  extern __shared__ char smem[];
  const uint32_t sb = smem_u32(smem);
  const int tid = threadIdx.x;
  const int wid = tid >> 5, lane = tid & 31;
  const int tile = blockIdx.x;
  const int rows = 9*N;
  const int t0 = N >> 7, t1 = t0*4;
  const int l = (tile < t0) ? 0 : ((tile < t1) ? 1 : 2);

  { // async stage W[l] (full 128 rows, hi only, padded)
    const char* srcH = (const char*)(Whi + (size_t)l*CCH*CCH);
    #pragma unroll
    for(int i=0;i<4;i++){
      int j = tid + i*512;                 // 2048 16B-chunks = 128 rows x 16
      int row = j >> 4, chunk = j & 15;
      CP_ASYNC16(sb + G1_OFF_W + row*(PADC*2) + chunk*16, srcH + row*256 + chunk*16);
    }
    asm volatile("cp.async.commit_group;");
  }
  if(tid < 128) *reinterpret_cast<float*>(smem + G1_OFF_BIAS + tid*4) = bias[tid];

  // stage A (fp32 -> fp16 hi, padded)
  #pragma unroll
  for(int i=0;i<8;i++){
    int j = tid + i*512;            // 4096 float4 = 128 rows x 32
    int row = j >> 5, col4 = j & 31;
    int R = tile*128 + row;
    float4 v = make_float4(0.f,0.f,0.f,0.f);
    if(R < rows){
      int n, m; row_to_nm(R, N, n, m);
      v = reinterpret_cast<const float4*>(x)[ ((size_t)n*MTOT + m)*32 + col4 ];
    }
    uint2 hp;
    hp.x = __half_as_ushort(__float2half_rn(v.x)) | ((uint32_t)__half_as_ushort(__float2half_rn(v.y)) << 16);
    hp.y = __half_as_ushort(__float2half_rn(v.z)) | ((uint32_t)__half_as_ushort(__float2half_rn(v.w)) << 16);
    *reinterpret_cast<uint2*>(smem + G1_OFF_A + row*(PADC*2) + col4*8) = hp;
  }
  asm volatile("cp.async.wait_group 0;");
  __syncthreads();

  // warp tile: rows mrow0..+16, cols ncol0..+64
  const int mrow0 = (wid >> 1)*16, ncol0 = (wid & 1)*64;
  const int g = lane >> 2, t = lane & 3;
  const int lr = lane & 7, aw = lane >> 3;
  const uint32_t aBase = sb + G1_OFF_A + (mrow0 + lr + (aw & 1)*8)*(PADC*2) + ((aw >> 1)*8)*2;
  const uint32_t bBase = sb + G1_OFF_W + (ncol0 + ((lane >> 4) << 3) + lr)*(PADC*2) + (((lane >> 3) & 1)*8)*2;

  float acc[32];
  #pragma unroll
  for(int i=0;i<32;i++) acc[i] = 0.f;

  #pragma unroll
  for(int ks=0; ks<8; ks++){
    const uint32_t ko = ks*32;
    uint32_t aH[4];
    LDSM4(aH, aBase + ko);
    #pragma unroll
    for(int ntp=0; ntp<4; ntp++){
      uint32_t bH[4];
      LDSM4(bH, bBase + ntp*16*(PADC*2) + ko);
      mma16816(acc + (2*ntp  )*4, aH, bH);
      mma16816(acc + (2*ntp+1)*4, aH, bH+2);
    }
  }

  const float* sbias = reinterpret_cast<const float*>(smem + G1_OFF_BIAS);
  #pragma unroll
  for(int half=0; half<2; half++){
    const int R = tile*128 + mrow0 + g + half*8;
    if(R >= rows) continue;
    int n, m; row_to_nm(R, N, n, m);
    __half2* po16 = reinterpret_cast<__half2*>(out16 + ((size_t)n*MTOT + m)*CCH + ncol0);
    #pragma unroll
    for(int nt=0; nt<8; nt++){
      const int c0 = nt*8 + 2*t;
      float v0 = acc[nt*4 + half*2 + 0];
      float v1 = acc[nt*4 + half*2 + 1];
      if(m == 0){ v0 += sbias[ncol0 + c0]; v1 += sbias[ncol0 + c0 + 1]; }
      po16[c0 >> 1] = __floats2half2_rn(v0, v1);
    }
  }
}

// ======================================================================
// GEMM2: two-term split-A fp16 ((A_hi + A_lo) * W_hi), output fp32 + bias + PN.
// CTA: 128x128, 512 threads. smem: A 2x34816 + W 34816 + bias = 104960 -> 2 CTAs/SM.
// ======================================================================
#define G2_OFF_AH 0
#define G2_OFF_AL (128*PADC*2)            // 34816
#define G2_OFF_W  (2*128*PADC*2)          // 69632
#define G2_OFF_BIAS (3*128*PADC*2)        // 104448
#define G2_SMEM (G2_OFF_BIAS + 512)       // 104960

__global__ __launch_bounds__(512, 2)
void gemm2_kernel(const float* __restrict__ x, const __half* __restrict__ Whi,
                  const float* __restrict__ bias, float* __restrict__ out, int N)
{
  extern __shared__ char smem[];
  const uint32_t sb = smem_u32(smem);
  const int tid = threadIdx.x;
  const int wid = tid >> 5, lane = tid & 31;
  const int tile = blockIdx.x;
  const int rows = 9*N;
  const int t0 = N >> 7, t1 = t0*4;
  const int l = (tile < t0) ? 0 : ((tile < t1) ? 1 : 2);

  { // async stage W[l]
    const char* srcH = (const char*)(Whi + (size_t)l*CCH*CCH);
    #pragma unroll
    for(int i=0;i<4;i++){
      int j = tid + i*512;
      int row = j >> 4, chunk = j & 15;
      CP_ASYNC16(sb + G2_OFF_W + row*(PADC*2) + chunk*16, srcH + row*256 + chunk*16);
    }
    asm volatile("cp.async.commit_group;");
  }
  if(tid < 128) *reinterpret_cast<float*>(smem + G2_OFF_BIAS + tid*4) = bias[tid];

  // stage A (fp32 -> split fp16 hi/lo)
  #pragma unroll
  for(int i=0;i<8;i++){
    int j = tid + i*512;
    int row = j >> 5, col4 = j & 31;
    int R = tile*128 + row;
    float4 v = make_float4(0.f,0.f,0.f,0.f);
    if(R < rows){
      int n, m; row_to_nm(R, N, n, m);
      v = reinterpret_cast<const float4*>(x)[ ((size_t)n*MTOT + m)*32 + col4 ];
    }
    __half h0 = __float2half_rn(v.x), h1 = __float2half_rn(v.y);
    __half h2 = __float2half_rn(v.z), h3 = __float2half_rn(v.w);
    __half l0 = __float2half_rn(v.x - __half2float(h0));
    __half l1 = __float2half_rn(v.y - __half2float(h1));
    __half l2 = __float2half_rn(v.z - __half2float(h2));
    __half l3 = __float2half_rn(v.w - __half2float(h3));
    uint2 hp, lp;
    hp.x = __half_as_ushort(h0) | ((uint32_t)__half_as_ushort(h1) << 16);
    hp.y = __half_as_ushort(h2) | ((uint32_t)__half_as_ushort(h3) << 16);
    lp.x = __half_as_ushort(l0) | ((uint32_t)__half_as_ushort(l1) << 16);
    lp.y = __half_as_ushort(l2) | ((uint32_t)__half_as_ushort(l3) << 16);
    *reinterpret_cast<uint2*>(smem + G2_OFF_AH + row*(PADC*2) + col4*8) = hp;
    *reinterpret_cast<uint2*>(smem + G2_OFF_AL + row*(PADC*2) + col4*8) = lp;
  }
  asm volatile("cp.async.wait_group 0;");
  __syncthreads();

  const int mrow0 = (wid >> 1)*16, ncol0 = (wid & 1)*64;
  const int g = lane >> 2, t = lane & 3;
  const int lr = lane & 7, aw = lane >> 3;
  const uint32_t aoff = (mrow0 + lr + (aw & 1)*8)*(PADC*2) + ((aw >> 1)*8)*2;
  const uint32_t aHBase = sb + G2_OFF_AH + aoff;
  const uint32_t aLBase = sb + G2_OFF_AL + aoff;
  const uint32_t bBase  = sb + G2_OFF_W + (ncol0 + ((lane >> 4) << 3) + lr)*(PADC*2) + (((lane >> 3) & 1)*8)*2;

  float acc[32];
  #pragma unroll
  for(int i=0;i<32;i++) acc[i] = 0.f;

  #pragma unroll
  for(int ks=0; ks<8; ks++){
    const uint32_t ko = ks*32;
    uint32_t aH[4], aL[4];
    LDSM4(aH, aHBase + ko);
    LDSM4(aL, aLBase + ko);
    #pragma unroll
    for(int ntp=0; ntp<4; ntp++){
      uint32_t bH[4];
      LDSM4(bH, bBase + ntp*16*(PADC*2) + ko);
      mma16816(acc + (2*ntp  )*4, aH, bH);
      mma16816(acc + (2*ntp  )*4, aL, bH);
      mma16816(acc + (2*ntp+1)*4, aH, bH+2);
      mma16816(acc + (2*ntp+1)*4, aL, bH+2);
    }
  }

  const float* sbias = reinterpret_cast<const float*>(smem + G2_OFF_BIAS);
  #pragma unroll
  for(int half=0; half<2; half++){
    const int R = tile*128 + mrow0 + g + half*8;
    if(R >= rows) continue;
    int n, m; row_to_nm(R, N, n, m);
    float pn = (m==0) ? 1.0f : ((m<4) ? 0.57735026918962576f : 0.70710678118654752f);
    float* po = out + ((size_t)n*MTOT + m)*CCH + ncol0;
    #pragma unroll
    for(int nt=0; nt<8; nt++){
      const int c0 = nt*8 + 2*t;
      float v0 = acc[nt*4 + half*2 + 0];
      float v1 = acc[nt*4 + half*2 + 1];
      if(m == 0){ v0 += sbias[ncol0 + c0]; v1 += sbias[ncol0 + c0 + 1]; }
      *reinterpret_cast<float2*>(po + c0) = make_float2(v0*pn, v1*pn);
    }
  }
}

// ======================================================================
// Device: contract accumulated outer-product tensor P with w3j + tpw.
// ======================================================================
__device__ __forceinline__ void contract_point(const float* p0, const float* p1, const float* p2,
                                               const float* tpw, const W3J& w, float* o){
  #pragma unroll
  for(int m=0;m<MTOT;m++) o[m]=0.0f;
  #pragma unroll
  for(int c=0;c<3;c++){
    float t=0.f;
    #pragma unroll
    for(int b=0;b<3;b++) t = fmaf(w.v[0 + b*3 + c], p0[b], t);
    o[1+c] = fmaf(tpw[0], t, o[1+c]);
  }
  {
    float t=0.f;
    #pragma unroll
    for(int a=0;a<3;a++)
      #pragma unroll
      for(int b=0;b<3;b++) t = fmaf(w.v[9 + a*3 + b], p1[a*3+b], t);
    o[0] = fmaf(tpw[1], t, o[0]);
  }
  #pragma unroll
  for(int c=0;c<3;c++){
    float t=0.f;
    #pragma unroll
    for(int a=0;a<3;a++)
      #pragma unroll
      for(int b=0;b<3;b++) t = fmaf(w.v[18 + (a*3+b)*3 + c], p1[a*3+b], t);
    o[1+c] = fmaf(tpw[2], t, o[1+c]);
  }
  #pragma unroll
  for(int c=0;c<5;c++){
    float t=0.f;
    #pragma unroll
    for(int a=0;a<3;a++)
      #pragma unroll
      for(int b=0;b<3;b++) t = fmaf(w.v[45 + (a*3+b)*5 + c], p1[a*3+b], t);
    o[4+c] = fmaf(tpw[3], t, o[4+c]);
  }
  #pragma unroll
  for(int c=0;c<3;c++){
    float t=0.f;
    #pragma unroll
    for(int a=0;a<5;a++)
      #pragma unroll
      for(int b=0;b<3;b++) t = fmaf(w.v[90 + (a*3+b)*3 + c], p2[a*3+b], t);
    o[1+c] = fmaf(tpw[4], t, o[1+c]);
  }
  #pragma unroll
  for(int c=0;c<5;c++){
    float t=0.f;
    #pragma unroll
    for(int a=0;a<5;a++)
      #pragma unroll
      for(int b=0;b<3;b++) t = fmaf(w.v[135 + (a*3+b)*5 + c], p2[a*3+b], t);
    o[4+c] = fmaf(tpw[5], t, o[4+c]);
  }
}

// ======================================================================
// Fully fused gather:
//   cdiff[b] = contract(w3j, sum_j a_j * h1[n_j] (x) (y_b - ey_{n_j})) . tpw
// ======================================================================
__global__ __launch_bounds__(256)
void gather_kernel(const __half* __restrict__ h1f,
                   const float* __restrict__ pos, const float* __restrict__ exp_pos,
                   const float* __restrict__ alpha, const int* __restrict__ idx,
                   const float* __restrict__ tp_w,
                   float* __restrict__ cdiff, int N1, W3J w, float scale)
{
  const int b = blockIdx.x*4 + (threadIdx.x >> 6);
  if(b >= N1) return;
  const int t = threadIdx.x & 63;
  const int c0 = 2*t;
  const int h = c0 >> 4;

  float2 P[MTOT][3];
  #pragma unroll
  for(int m=0;m<MTOT;m++)
    #pragma unroll
    for(int k=0;k<3;k++) P[m][k] = make_float2(0.f, 0.f);

  float yb[3];
  #pragma unroll
  for(int k=0;k<3;k++) yb[k] = scale * pos[b*3+k];

  const int*   ib = idx   + (size_t)b*KNB;
  const float* ab = alpha + (size_t)b*KNB*HH;

  #pragma unroll 2
  for(int j=0;j<KNB;j++){
    const int n = ib[j];
    const float a = ab[j*HH + h];
    float ady[3];
    #pragma unroll
    for(int k=0;k<3;k++) ady[k] = a * (yb[k] - scale * exp_pos[n*3+k]);
    const __half2* px = reinterpret_cast<const __half2*>(h1f + (size_t)n*MTOT*CCH) + t;
    #pragma unroll
    for(int m=0;m<MTOT;m++){
      float2 v = __half22float2(px[m*64]);
      #pragma unroll
      for(int k=0;k<3;k++){
        P[m][k].x = fmaf(v.x, ady[k], P[m][k].x);
        P[m][k].y = fmaf(v.y, ady[k], P[m][k].y);
      }
    }
  }

  float tpw0[6], tpw1[6];
  #pragma unroll
  for(int p=0;p<6;p++){
    float2 v = *reinterpret_cast<const float2*>(tp_w + p*CCH + c0);
    tpw0[p] = v.x; tpw1[p] = v.y;
  }

  float p0[3], p1[9], p2[15], o0[MTOT], o1[MTOT];
  #pragma unroll
  for(int k=0;k<3;k++) p0[k] = P[0][k].x;
  #pragma unroll
  for(int a2=0;a2<3;a2++)
    #pragma unroll
    for(int k=0;k<3;k++) p1[a2*3+k] = P[1+a2][k].x;
  #pragma unroll
  for(int a2=0;a2<5;a2++)
    #pragma unroll
    for(int k=0;k<3;k++) p2[a2*3+k] = P[4+a2][k].x;
  contract_point(p0, p1, p2, tpw0, w, o0);
  #pragma unroll
  for(int k=0;k<3;k++) p0[k] = P[0][k].y;
  #pragma unroll
  for(int a2=0;a2<3;a2++)
    #pragma unroll
    for(int k=0;k<3;k++) p1[a2*3+k] = P[1+a2][k].y;
  #pragma unroll
  for(int a2=0;a2<5;a2++)
    #pragma unroll
    for(int k=0;k<3;k++) p2[a2*3+k] = P[4+a2][k].y;
  contract_point(p0, p1, p2, tpw1, w, o1);

  float* od = cdiff + (size_t)b*MTOT*CCH + c0;
  #pragma unroll
  for(int m=0;m<MTOT;m++)
    *reinterpret_cast<float2*>(od + m*CCH) = make_float2(o0[m], o1[m]);
}

// ======================================================================
// launch
// ======================================================================
extern "C" void kernel_launch(void* const* d_in, const int* in_sizes, int n_in,
                              void* d_out, int out_size)
{
  const float* pos     = (const float*)d_in[0];
  const float* exp_pos = (const float*)d_in[1];
  // d_in[2] = h : unused by the reference
  const float* exp_h   = (const float*)d_in[3];
  const float* alpha   = (const float*)d_in[4];
  const int*   idx     = (const int*)  d_in[5];
  const float* w1w     = (const float*)d_in[6];
  const float* w1b     = (const float*)d_in[7];
  const float* w2w     = (const float*)d_in[8];
  const float* w2b     = (const float*)d_in[9];
  const float* tpw     = (const float*)d_in[10];

  const int N1 = in_sizes[0]/3;
  const int N2 = in_sizes[1]/3;

  W3J w;
  build_w3j(&w);
  const double PI = 3.14159265358979323846;
  const float scale = (float)(2.04665350914 * std::sqrt(3.0/(4.0*PI)));  // COEF1 * SH1_INT

  float *p_cd=nullptr;
  __half *p_h1f=nullptr, *p_whi=nullptr;
  cudaGetSymbolAddress((void**)&p_cd,  g_cdiff);
  cudaGetSymbolAddress((void**)&p_h1f, g_h1f16);
  cudaGetSymbolAddress((void**)&p_whi, g_Whi);

  cudaFuncSetAttribute(gemm1_kernel, cudaFuncAttributeMaxDynamicSharedMemorySize, G1_SMEM);
  cudaFuncSetAttribute(gemm2_kernel, cudaFuncAttributeMaxDynamicSharedMemorySize, G2_SMEM);

  const int tiles2 = (9*N2 + 127) >> 7;   // 288 for N2=4096
  const int tiles1 = (9*N1 + 127) >> 7;

  // 0) W images (both linears, fp16, transposed)
  conv_w_kernel<<<(2*3*CCH*CCH + 255)/256, 256>>>(w1w, w2w, p_whi);
  // 1) h1f16 = fp16( so3_linear(exp_h, w1) )
  gemm1_kernel<<<tiles2, 512, G1_SMEM>>>(exp_h, p_whi, w1b, p_h1f, N2);
  // 2) fused gather + both tensor products via bilinearity
  gather_kernel<<<(N1+3)/4, 256>>>(p_h1f, pos, exp_pos, alpha, idx, tpw, p_cd, N1, w, scale);
  // 3) out = so3_linear(cdiff, w2) * PATH_NORM
  gemm2_kernel<<<tiles1, 512, G2_SMEM>>>(p_cd, p_whi + 3*CCH*CCH, w2b, (float*)d_out, N1);
}